// round 14
// baseline (speedup 1.0000x reference)
#include <cuda_runtime.h>
#include <cuda_bf16.h>
#include <cstdint>

#define H_    512
#define B_    128
#define T_    512
#define L_    4
#define J_    2
#define NBLK  256
#define NTHR  256

// ---- stage-1 smem slot (3-slot ring): A 32x128k hi/lo, W 32x128k hi/lo ----
#define S1_ROWB 272
#define S1_A_LO 8704
#define S1_W_HI 17408
#define S1_W_LO 26112
#define S1_SZ   34816
// ---- stage-2 smem slot (3-slot ring): A 16x128k hi/lo, W 32x128k hi/lo ----
#define S2_ROWB 272
#define S2_A_LO 4352
#define S2_W_HI 8704
#define S2_W_LO 17408
#define S2_SZ   26112
// ---- partial-sum scratch (shared by both stages, after stage-1 ring) ----
#define P_OFF   104448              // 3*S1_SZ
#define SMEM_TOTAL (P_OFF + 8192)   // 112640 -> 2 CTAs/SM

// ---- converted weights (bf16 hi/lo, transposed to [n][k]) ----
__device__ __nv_bfloat16 d_linw_h[8u * 2048u * 1024u];
__device__ __nv_bfloat16 d_linw_l[8u * 2048u * 1024u];
__device__ __nv_bfloat16 d_gw_h[8u * 1024u * 1024u];   // n<512: g0w, n>=512: g1w
__device__ __nv_bfloat16 d_gw_l[8u * 1024u * 1024u];

// ---- fp32 state ----
__device__ __align__(128) float d_z[B_ * 1024];        // z0 | z1
__device__ __align__(128) float d_h0buf[2][B_ * H_];
__device__ __align__(128) float d_h1buf[2][B_ * H_];
__device__ __align__(128) float d_H1[L_ * B_ * H_];
// ---- pre-split bf16 hi/lo GEMM A operands ----
__device__ __align__(128) __nv_bfloat16 d_x0h[B_ * H_], d_x0l[B_ * H_];
__device__ __align__(128) __nv_bfloat16 d_h0h[2][B_ * H_], d_h0l[2][B_ * H_];
__device__ __align__(128) __nv_bfloat16 d_h1h[2][B_ * H_], d_h1l[2][B_ * H_];
__device__ __align__(128) __nv_bfloat16 d_H1h[L_ * B_ * H_], d_H1l[L_ * B_ * H_];
__device__ __align__(128) __nv_bfloat16 d_arh[B_ * H_], d_arl[B_ * H_];
__device__ __align__(128) __nv_bfloat16 d_aqh[B_ * H_], d_aql[B_ * H_];
__device__ unsigned int g_bar = 0;

// ================= helpers =================
__device__ __forceinline__ uint32_t smem_u32(const void* p) {
    uint32_t a;
    asm("{ .reg .u64 t; cvta.to.shared.u64 t, %1; cvt.u32.u64 %0, t; }"
        : "=r"(a) : "l"(p));
    return a;
}
__device__ __forceinline__ void cpa16(uint32_t d, const void* s) {
    asm volatile("cp.async.cg.shared.global [%0], [%1], 16;" :: "r"(d), "l"(s));
}
__device__ __forceinline__ void cp_commit() {
    asm volatile("cp.async.commit_group;" ::: "memory");
}
template <int N>
__device__ __forceinline__ void cp_wait() {
    asm volatile("cp.async.wait_group %0;" :: "n"(N) : "memory");
}
__device__ __forceinline__ void ldm_x4(uint32_t* r, uint32_t addr) {
    asm volatile("ldmatrix.sync.aligned.m8n8.x4.shared.b16 {%0,%1,%2,%3}, [%4];"
                 : "=r"(r[0]), "=r"(r[1]), "=r"(r[2]), "=r"(r[3]) : "r"(addr));
}
__device__ __forceinline__ void mma16816(float* c, const uint32_t* a, const uint32_t* b) {
    asm volatile(
        "mma.sync.aligned.m16n8k16.row.col.f32.bf16.bf16.f32 "
        "{%0,%1,%2,%3}, {%4,%5,%6,%7}, {%8,%9}, {%0,%1,%2,%3};"
        : "+f"(c[0]), "+f"(c[1]), "+f"(c[2]), "+f"(c[3])
        : "r"(a[0]), "r"(a[1]), "r"(a[2]), "r"(a[3]), "r"(b[0]), "r"(b[1]));
}
__device__ __forceinline__ void split2(float x, unsigned short& h, unsigned short& l) {
    __nv_bfloat16 hb = __float2bfloat16(x);
    float r = x - __bfloat162float(hb);
    __nv_bfloat16 lb = __float2bfloat16(r);
    h = *reinterpret_cast<unsigned short*>(&hb);
    l = *reinterpret_cast<unsigned short*>(&lb);
}
__device__ __forceinline__ void split_pack(float x, float y, uint32_t& hi, uint32_t& lo) {
    unsigned short hx, lx, hy, ly;
    split2(x, hx, lx); split2(y, hy, ly);
    hi = (uint32_t)hx | ((uint32_t)hy << 16);
    lo = (uint32_t)lx | ((uint32_t)ly << 16);
}
__device__ __forceinline__ float sigf(float v) { return 1.f / (1.f + __expf(-v)); }
__device__ __forceinline__ void grid_barrier() {
    __syncthreads();
    if (threadIdx.x == 0) {
        __threadfence();
        unsigned ticket = atomicAdd(&g_bar, 1u);
        unsigned target = (ticket & ~(unsigned)(NBLK - 1)) + NBLK;
        while ((int)(*(volatile unsigned*)&g_bar - target) < 0) { __nanosleep(20); }
        __threadfence();
    }
    __syncthreads();
}

// ============ weight pre-conversion: fp32 [k][n] -> bf16 hi/lo [n][k] ============
__global__ void convert_weights(const float* __restrict__ lin_w,
                                const float* __restrict__ g0w,
                                const float* __restrict__ g1w) {
    int t = blockIdx.x * blockDim.x + threadIdx.x;
    const float* src;
    int stride;
    __nv_bfloat16 *dh, *dl;
    if (t < 8 * 2048) {
        int cell = t >> 11, n = t & 2047;
        src = lin_w + (size_t)cell * 1024 * 2048 + n;
        stride = 2048;
        dh = d_linw_h + (size_t)t * 1024;
        dl = d_linw_l + (size_t)t * 1024;
    } else {
        int t2 = t - 8 * 2048;
        if (t2 >= 8 * 1024) return;
        int cell = t2 >> 10, n = t2 & 1023;
        src = (n < 512) ? (g0w + (size_t)cell * 1024 * 512 + n)
                        : (g1w + (size_t)cell * 1024 * 512 + (n - 512));
        stride = 512;
        dh = d_gw_h + (size_t)t2 * 1024;
        dl = d_gw_l + (size_t)t2 * 1024;
    }
    for (int k0 = 0; k0 < 1024; k0 += 8) {
        unsigned short hb[8], lb[8];
#pragma unroll
        for (int i = 0; i < 8; ++i)
            split2(src[(size_t)(k0 + i) * stride], hb[i], lb[i]);
        *(uint4*)(dh + k0) = *(uint4*)hb;
        *(uint4*)(dl + k0) = *(uint4*)lb;
    }
}

// ====== stage-1 GEMM: C[32 x 32], warps 2m x 2n x 2k, warp tile 16x16 ======
// Publishes 2-way k-split partials to P[wk*1024 + m*32 + n].
__device__ __forceinline__ void gemm_s1(
    uint32_t smb, char* smraw, int mbase, int nbase,
    const __nv_bfloat16* __restrict__ a0h, const __nv_bfloat16* __restrict__ a0l,
    const __nv_bfloat16* __restrict__ a1h, const __nv_bfloat16* __restrict__ a1l,
    const __nv_bfloat16* __restrict__ wh,  const __nv_bfloat16* __restrict__ wl)
{
    const int tid = threadIdx.x, lane = tid & 31, wid = tid >> 5;
    const int wm = wid & 1, wn = (wid >> 1) & 1, wk = wid >> 2;  // 2m x 2n x 2k
    const int g = lane >> 2, tg = lane & 3;
    float acc[8];
#pragma unroll
    for (int i = 0; i < 8; ++i) acc[i] = 0.f;

    const uint32_t aOffH = (uint32_t)(wm * 16 + (lane & 15)) * S1_ROWB +
                           (lane >> 4) * 16 + wk * 128;
    const uint32_t aOffL = aOffH + S1_A_LO;
    const uint32_t wOffH = S1_W_HI +
                           (uint32_t)(wn * 16 + (lane & 7) + ((lane >> 4) & 1) * 8) *
                               S1_ROWB + ((lane >> 3) & 1) * 16 + wk * 128;
    const uint32_t wOffL = wOffH + (S1_W_LO - S1_W_HI);

    const int arow = tid >> 3, agr = (tid & 7) * 2;   // A: 32 rows x 2 granules
    const int wrow = tid >> 3, wgr = (tid & 7) * 2;   // W: 32 rows x 2 granules

    auto issue = [&](int kc) {
        const uint32_t st = smb + (uint32_t)(kc % 3) * S1_SZ;
        const __nv_bfloat16* ah = (kc < 4) ? a0h : a1h;
        const __nv_bfloat16* al = (kc < 4) ? a0l : a1l;
        const int koff = (kc & 3) * 128;
        const __nv_bfloat16* srh = ah + (size_t)(mbase + arow) * 512 + koff + agr * 8;
        const __nv_bfloat16* srl = al + (size_t)(mbase + arow) * 512 + koff + agr * 8;
        const uint32_t dA = st + (uint32_t)arow * S1_ROWB + agr * 16;
        cpa16(dA, srh);            cpa16(dA + 16, srh + 8);
        cpa16(dA + S1_A_LO, srl);  cpa16(dA + S1_A_LO + 16, srl + 8);
        const __nv_bfloat16* wsh = wh + (size_t)(nbase + wrow) * 1024 + kc * 128 + wgr * 8;
        const __nv_bfloat16* wsl = wl + (size_t)(nbase + wrow) * 1024 + kc * 128 + wgr * 8;
        const uint32_t dW = st + S1_W_HI + (uint32_t)wrow * S1_ROWB + wgr * 16;
        cpa16(dW, wsh);  cpa16(dW + 16, wsh + 8);
        cpa16(dW + (S1_W_LO - S1_W_HI), wsl);
        cpa16(dW + (S1_W_LO - S1_W_HI) + 16, wsl + 8);
        cp_commit();
    };

    issue(0); issue(1);
    for (int kc = 0; kc < 8; ++kc) {
        if (kc < 7) cp_wait<1>(); else cp_wait<0>();
        __syncthreads();
        if (kc + 2 < 8) issue(kc + 2);
        const uint32_t base = smb + (uint32_t)(kc % 3) * S1_SZ;
#pragma unroll
        for (int s = 0; s < 4; ++s) {
            uint32_t ah[4], al[4], bh[4], bl[4];
            ldm_x4(ah, base + aOffH + s * 32);
            ldm_x4(al, base + aOffL + s * 32);
            ldm_x4(bh, base + wOffH + s * 32);
            ldm_x4(bl, base + wOffL + s * 32);
            mma16816(acc,     ah, bh);
            mma16816(acc + 4, ah, bh + 2);
            mma16816(acc,     al, bh);
            mma16816(acc + 4, al, bh + 2);
            mma16816(acc,     ah, bl);
            mma16816(acc + 4, ah, bl + 2);
        }
    }
    // publish partials: P[wk(2)][m(32)][n(32)] -> plane stride 1024 floats
    float* P = (float*)(smraw + P_OFF);
#pragma unroll
    for (int nt = 0; nt < 2; ++nt)
#pragma unroll
        for (int rr = 0; rr < 2; ++rr) {
            const int m = wm * 16 + rr * 8 + g;
            const int n = wn * 16 + nt * 8 + tg * 2;
            *(float2*)&P[(wk << 10) + m * 32 + n] =
                make_float2(acc[nt * 4 + rr * 2], acc[nt * 4 + rr * 2 + 1]);
        }
    __syncthreads();
}

// ====== stage-2 GEMM: C[16 x 32], warps 2n x 4k, warp tile 16x16 ======
// Publishes 4-way k-split partials to P[wk*512 + m*32 + n].
__device__ __forceinline__ void gemm_s2(
    uint32_t smb, char* smraw, int mbase, int nbase,
    const __nv_bfloat16* __restrict__ s0h, const __nv_bfloat16* __restrict__ s0l,
    const __nv_bfloat16* __restrict__ s1h, const __nv_bfloat16* __restrict__ s1l,
    const __nv_bfloat16* __restrict__ wh,  const __nv_bfloat16* __restrict__ wl)
{
    const int tid = threadIdx.x, lane = tid & 31, wid = tid >> 5;
    const int wn = wid & 1, wk = wid >> 1;            // 2n x 4k
    const int g = lane >> 2, tg = lane & 3;
    float acc[8];
#pragma unroll
    for (int i = 0; i < 8; ++i) acc[i] = 0.f;

    const uint32_t aOffH = (uint32_t)(lane & 15) * S2_ROWB +
                           (lane >> 4) * 16 + wk * 64;
    const uint32_t aOffL = aOffH + S2_A_LO;
    const uint32_t wOffH = S2_W_HI +
                           (uint32_t)(wn * 16 + (lane & 7) + ((lane >> 4) & 1) * 8) *
                               S2_ROWB + ((lane >> 3) & 1) * 16 + wk * 64;
    const uint32_t wOffL = wOffH + (S2_W_LO - S2_W_HI);

    const int arow = tid >> 4, ag = tid & 15;         // A: 16 rows x 1 granule
    const int wrow = tid >> 3, wgr = (tid & 7) * 2;   // W: 32 rows x 2 granules

    auto issue = [&](int kc) {
        const uint32_t st = smb + (uint32_t)(kc % 3) * S2_SZ;
        const __nv_bfloat16* ph = (kc < 4) ? s0h : s1h;
        const __nv_bfloat16* pl = (kc < 4) ? s0l : s1l;
        const int koff = (kc & 3) * 128;
        const __nv_bfloat16* srh = ph + (size_t)(mbase + arow) * 512 + koff + ag * 8;
        const __nv_bfloat16* srl = pl + (size_t)(mbase + arow) * 512 + koff + ag * 8;
        const uint32_t dA = st + (uint32_t)arow * S2_ROWB + ag * 16;
        cpa16(dA, srh);
        cpa16(dA + S2_A_LO, srl);
        const __nv_bfloat16* wsh = wh + (size_t)(nbase + wrow) * 1024 + kc * 128 + wgr * 8;
        const __nv_bfloat16* wsl = wl + (size_t)(nbase + wrow) * 1024 + kc * 128 + wgr * 8;
        const uint32_t dW = st + S2_W_HI + (uint32_t)wrow * S2_ROWB + wgr * 16;
        cpa16(dW, wsh);  cpa16(dW + 16, wsh + 8);
        cpa16(dW + (S2_W_LO - S2_W_HI), wsl);
        cpa16(dW + (S2_W_LO - S2_W_HI) + 16, wsl + 8);
        cp_commit();
    };

    issue(0); issue(1);
    for (int kc = 0; kc < 8; ++kc) {
        if (kc < 7) cp_wait<1>(); else cp_wait<0>();
        __syncthreads();
        if (kc + 2 < 8) issue(kc + 2);
        const uint32_t base = smb + (uint32_t)(kc % 3) * S2_SZ;
#pragma unroll
        for (int s = 0; s < 2; ++s) {
            uint32_t ah[4], al[4], bh[4], bl[4];
            ldm_x4(ah, base + aOffH + s * 32);
            ldm_x4(al, base + aOffL + s * 32);
            ldm_x4(bh, base + wOffH + s * 32);
            ldm_x4(bl, base + wOffL + s * 32);
            mma16816(acc,     ah, bh);
            mma16816(acc + 4, ah, bh + 2);
            mma16816(acc,     al, bh);
            mma16816(acc + 4, al, bh + 2);
            mma16816(acc,     ah, bl);
            mma16816(acc + 4, ah, bl + 2);
        }
    }
    // publish partials: P[wk(4)][m(16)][n(32)] -> plane stride 512 floats
    float* P = (float*)(smraw + P_OFF);
#pragma unroll
    for (int nt = 0; nt < 2; ++nt)
#pragma unroll
        for (int rr = 0; rr < 2; ++rr) {
            const int m = rr * 8 + g;
            const int n = wn * 16 + nt * 8 + tg * 2;
            *(float2*)&P[(wk << 9) + m * 32 + n] =
                make_float2(acc[nt * 4 + rr * 2], acc[nt * 4 + rr * 2 + 1]);
        }
    __syncthreads();
}

// =================== main persistent kernel ===================
__global__ void __launch_bounds__(NTHR, 2) lattice_mma(
    const float* __restrict__ H0in,
    const float* __restrict__ lin_b,
    const float* __restrict__ g0b, const float* __restrict__ g1b,
    float* __restrict__ out)
{
    extern __shared__ __align__(16) char smraw[];
    const uint32_t smb = smem_u32(smraw);

    const int tid = threadIdx.x;
    const int blk = blockIdx.x;

    for (int i = tid + blk * NTHR; i < L_ * B_ * H_; i += NBLK * NTHR) {
        d_H1[i] = 0.f;
        d_H1h[i] = __float2bfloat16(0.f);
        d_H1l[i] = __float2bfloat16(0.f);
    }
    for (int e = tid + blk * NTHR; e < B_ * H_; e += NBLK * NTHR) {
        int b = e >> 9, h = e & (H_ - 1);
        float v = __ldg(&H0in[(size_t)b * T_ * H_ + h]);
        unsigned short hh, ll;
        split2(v, hh, ll);
        d_x0h[e] = *reinterpret_cast<__nv_bfloat16*>(&hh);
        d_x0l[e] = *reinterpret_cast<__nv_bfloat16*>(&ll);
    }
    grid_barrier();

    float* out_h1 = out + (size_t)B_ * T_ * H_;

    // tile coords
    const int m1base = (blk & 3) * 32, n1base = (blk >> 2) * 32;
    const int m2base = (blk & 7) * 16, n2base = (blk >> 3) * 32;
    const bool g0side = (n2base < 512);
    const int region = n1base >> 9;          // 0,1: z   2: r   3: q

    // cooperative-epilogue coordinates
    const int e1m = tid >> 3, e1n = (tid & 7) * 4;     // stage 1: 32x32 / 256
    const int e2m = tid >> 4, e2n = (tid & 15) * 2;    // stage 2: 16x32 / 256

    for (int t = 0; t < T_; ++t) {
        int p = 0;
        for (int l = 0; l < L_; ++l) {
            for (int j = 0; j < J_; ++j) {
                const int  cell  = l * J_ + j;
                const bool first = (l == 0 && j == 0);
                const bool last  = (l == L_ - 1 && j == J_ - 1);

                const float* h0src = first ? (H0in + (size_t)t * H_) : d_h0buf[p];
                const int    lda0  = first ? (T_ * H_) : H_;
                const float* h1src = (j == 0) ? (d_H1 + (size_t)l * B_ * H_) : d_h1buf[p];
                float*       h0dst = last ? (out + (size_t)t * H_) : d_h0buf[p ^ 1];
                const int    ldh0d = last ? (T_ * H_) : H_;
                float*       h1dst = (j == J_ - 1) ? (d_H1 + (size_t)l * B_ * H_)
                                                   : d_h1buf[p ^ 1];
                const __nv_bfloat16* h0sh = first ? d_x0h : d_h0h[p];
                const __nv_bfloat16* h0sl = first ? d_x0l : d_h0l[p];
                const __nv_bfloat16* h1sh = (j == 0) ? (d_H1h + (size_t)l * B_ * H_)
                                                     : d_h1h[p];
                const __nv_bfloat16* h1sl = (j == 0) ? (d_H1l + (size_t)l * B_ * H_)
                                                     : d_h1l[p];
                __nv_bfloat16* h1dh = (j == J_ - 1) ? (d_H1h + (size_t)l * B_ * H_)
                                                    : d_h1h[p ^ 1];
                __nv_bfloat16* h1dl = (j == J_ - 1) ? (d_H1l + (size_t)l * B_ * H_)
                                                    : d_h1l[p ^ 1];
                __nv_bfloat16* h0dh = d_h0h[p ^ 1];
                __nv_bfloat16* h0dl = d_h0l[p ^ 1];

                // ---------- stage 1: gate GEMM (32x32) + cooperative epilogue ----
                {
                    gemm_s1(smb, smraw, m1base, n1base,
                            h0sh, h0sl, h1sh, h1sl,
                            d_linw_h + (size_t)cell * 2048 * 1024,
                            d_linw_l + (size_t)cell * 2048 * 1024);

                    const float* P = (const float*)(smraw + P_OFF);
                    float4 p0 = *(const float4*)&P[e1m * 32 + e1n];
                    float4 p1 = *(const float4*)&P[1024 + e1m * 32 + e1n];
                    const int   mrow = m1base + e1m;
                    const int   col  = n1base + e1n;
                    const float* bp  = lin_b + (size_t)cell * 2048 + col;
                    const float s0 = sigf(p0.x + p1.x + bp[0]);
                    const float s1 = sigf(p0.y + p1.y + bp[1]);
                    const float s2 = sigf(p0.z + p1.z + bp[2]);
                    const float s3 = sigf(p0.w + p1.w + bp[3]);
                    if (region < 2) {
                        *(float4*)&d_z[mrow * 1024 + col] =
                            make_float4(s0, s1, s2, s3);
                    } else if (region == 2) {
                        const int cc = col - 1024;
                        float4 h = __ldcg((const float4*)&h1src[mrow * H_ + cc]);
                        uint32_t h01, l01, h23, l23;
                        split_pack(s0 * h.x, s1 * h.y, h01, l01);
                        split_pack(s2 * h.z, s3 * h.w, h23, l23);
                        *(uint2*)&d_arh[mrow * H_ + cc] = make_uint2(h01, h23);
                        *(uint2*)&d_arl[mrow * H_ + cc] = make_uint2(l01, l23);
                    } else {
                        const int cc = col - 1536;
                        float4 h = __ldcg((const float4*)&h0src[(size_t)mrow * lda0 + cc]);
                        uint32_t h01, l01, h23, l23;
                        split_pack(s0 * h.x, s1 * h.y, h01, l01);
                        split_pack(s2 * h.z, s3 * h.w, h23, l23);
                        *(uint2*)&d_aqh[mrow * H_ + cc] = make_uint2(h01, h23);
                        *(uint2*)&d_aql[mrow * H_ + cc] = make_uint2(l01, l23);
                    }
                }
                grid_barrier();

                // ---------- stage 2: candidate GEMM (16x32) + coop epilogue ----
                {
                    const __nv_bfloat16* a0h = g0side ? h0sh : h1sh;
                    const __nv_bfloat16* a0l = g0side ? h0sl : h1sl;
                    const __nv_bfloat16* a1h = g0side ? d_arh : d_aqh;
                    const __nv_bfloat16* a1l = g0side ? d_arl : d_aql;
                    gemm_s2(smb, smraw, m2base, n2base,
                            a0h, a0l, a1h, a1l,
                            d_gw_h + (size_t)cell * 1024 * 1024,
                            d_gw_l + (size_t)cell * 1024 * 1024);

                    const float* P = (const float*)(smraw + P_OFF);
                    float2 q0 = *(const float2*)&P[e2m * 32 + e2n];
                    float2 q1 = *(const float2*)&P[512 + e2m * 32 + e2n];
                    float2 q2 = *(const float2*)&P[1024 + e2m * 32 + e2n];
                    float2 q3 = *(const float2*)&P[1536 + e2m * 32 + e2n];
                    const float v0 = q0.x + q1.x + q2.x + q3.x;
                    const float v1 = q0.y + q1.y + q2.y + q3.y;
                    const int mrow = m2base + e2m;
                    const int col  = n2base + e2n;
                    if (g0side) {
                        const float* bp = g0b + (size_t)cell * H_ + col;
                        const float c0 = tanhf(v0 + bp[0]);
                        const float c1 = tanhf(v1 + bp[1]);
                        float2 z = __ldcg((const float2*)&d_z[mrow * 1024 + H_ + col]);
                        float2 o = __ldcg((const float2*)&h1src[mrow * H_ + col]);
                        const float n0v = z.x * c0 + (1.f - z.x) * o.x;
                        const float n1v = z.y * c1 + (1.f - z.y) * o.y;
                        *(float2*)&h1dst[mrow * H_ + col] = make_float2(n0v, n1v);
                        uint32_t hi, lo;
                        split_pack(n0v, n1v, hi, lo);
                        *(uint32_t*)&h1dh[mrow * H_ + col] = hi;
                        *(uint32_t*)&h1dl[mrow * H_ + col] = lo;
                    } else {
                        const int n2 = col - 512;
                        const float* bp = g1b + (size_t)cell * H_ + n2;
                        const float c0 = tanhf(v0 + bp[0]);
                        const float c1 = tanhf(v1 + bp[1]);
                        float2 z = __ldcg((const float2*)&d_z[mrow * 1024 + n2]);
                        float2 o = __ldcg((const float2*)&h0src[(size_t)mrow * lda0 + n2]);
                        const float n0v = z.x * c0 + (1.f - z.x) * o.x;
                        const float n1v = z.y * c1 + (1.f - z.y) * o.y;
                        *(float2*)&h0dst[(size_t)mrow * ldh0d + n2] =
                            make_float2(n0v, n1v);
                        if (!last) {
                            uint32_t hi, lo;
                            split_pack(n0v, n1v, hi, lo);
                            *(uint32_t*)&h0dh[mrow * H_ + n2] = hi;
                            *(uint32_t*)&h0dl[mrow * H_ + n2] = lo;
                        }
                    }
                    if (last && t + 1 < T_) {
                        for (int e = tid + blk * NTHR; e < B_ * H_; e += NBLK * NTHR) {
                            int b = e >> 9, h = e & (H_ - 1);
                            float v = __ldg(&H0in[((size_t)b * T_ + (t + 1)) * H_ + h]);
                            unsigned short hh, ll;
                            split2(v, hh, ll);
                            d_x0h[e] = *reinterpret_cast<__nv_bfloat16*>(&hh);
                            d_x0l[e] = *reinterpret_cast<__nv_bfloat16*>(&ll);
                        }
                    }
                }
                grid_barrier();
                p ^= 1;
            }
        }
    }

    for (int i = tid + blk * NTHR; i < L_ * B_ * H_; i += NBLK * NTHR) {
        int h    = i & (H_ - 1);
        int rest = i >> 9;
        int b    = rest & (B_ - 1);
        int l    = rest >> 7;
        out_h1[((size_t)b * L_ + l) * H_ + h] = __ldcg(&d_H1[i]);
    }
}

extern "C" void kernel_launch(void* const* d_in, const int* in_sizes, int n_in,
                              void* d_out, int out_size)
{
    const float* H0in  = (const float*)d_in[0];
    const float* lin_w = (const float*)d_in[1];
    const float* lin_b = (const float*)d_in[2];
    const float* g0w   = (const float*)d_in[3];
    const float* g0b   = (const float*)d_in[4];
    const float* g1w   = (const float*)d_in[5];
    const float* g1b   = (const float*)d_in[6];

    cudaFuncSetAttribute(lattice_mma,
                         cudaFuncAttributeMaxDynamicSharedMemorySize, SMEM_TOTAL);

    convert_weights<<<96, 256>>>(lin_w, g0w, g1w);
    lattice_mma<<<NBLK, NTHR, SMEM_TOTAL>>>(H0in, lin_b, g0b, g1b, (float*)d_out);
}

// round 15
// speedup vs baseline: 1.1484x; 1.1484x over previous
#include <cuda_runtime.h>
#include <cuda_bf16.h>
#include <cstdint>

#define H_    512
#define B_    128
#define T_    512
#define L_    4
#define J_    2
#define NBLK  128
#define NTHR  512
#define BH    (B_ * H_)

// ---- stage-1 smem layout (per pipeline slot, bytes), 3-slot ring ----
#define S1_ROWB 272
#define S1_A_LO 17408
#define S1_W_HI 34816
#define S1_W_LO 43520
#define S1_SZ   52224
// ---- stage-2 smem layout, 3-slot ring ----
#define S2_ROWB 528
#define S2_A_LO 16896
#define S2_W_HI 33792
#define S2_W_LO 50688
#define S2_SZ   67584
#define P_OFF   156672               // 3*S1_SZ: stage-1 partial scratch
#define SMEM_TOTAL (3 * S2_SZ)       // 202752

// ---- converted weights (bf16 hi/lo, transposed to [n][k]) ----
__device__ __nv_bfloat16 d_linw_h[8u * 2048u * 1024u];
__device__ __nv_bfloat16 d_linw_l[8u * 2048u * 1024u];
__device__ __nv_bfloat16 d_gw_h[8u * 1024u * 1024u];   // n<512: g0w, n>=512: g1w
__device__ __nv_bfloat16 d_gw_l[8u * 1024u * 1024u];

// ---- per-layer wavefront state ----
__device__ __align__(128) float d_zL[L_][B_ * 1024];
__device__ __align__(128) float d_h0mid[L_][BH], d_h1mid[L_][BH];
__device__ __align__(128) float d_h0out[2][L_][BH];
__device__ __align__(128) float d_H1[L_][BH];
__device__ __align__(128) __nv_bfloat16 d_h0midh[L_][BH], d_h0midl[L_][BH];
__device__ __align__(128) __nv_bfloat16 d_h1midh[L_][BH], d_h1midl[L_][BH];
__device__ __align__(128) __nv_bfloat16 d_h0outh[2][L_][BH], d_h0outl[2][L_][BH];
__device__ __align__(128) __nv_bfloat16 d_H1h[L_][BH], d_H1l[L_][BH];
__device__ __align__(128) __nv_bfloat16 d_x0h[2][BH], d_x0l[2][BH];
__device__ __align__(128) __nv_bfloat16 d_arh[L_][BH], d_arl[L_][BH];
__device__ __align__(128) __nv_bfloat16 d_aqh[L_][BH], d_aql[L_][BH];
__device__ unsigned int g_bar = 0;

// ================= helpers =================
__device__ __forceinline__ uint32_t smem_u32(const void* p) {
    uint32_t a;
    asm("{ .reg .u64 t; cvta.to.shared.u64 t, %1; cvt.u32.u64 %0, t; }"
        : "=r"(a) : "l"(p));
    return a;
}
__device__ __forceinline__ void cpa16(uint32_t d, const void* s) {
    asm volatile("cp.async.cg.shared.global [%0], [%1], 16;" :: "r"(d), "l"(s));
}
__device__ __forceinline__ void cp_commit() {
    asm volatile("cp.async.commit_group;" ::: "memory");
}
template <int N>
__device__ __forceinline__ void cp_wait() {
    asm volatile("cp.async.wait_group %0;" :: "n"(N) : "memory");
}
__device__ __forceinline__ void ldm_x4(uint32_t* r, uint32_t addr) {
    asm volatile("ldmatrix.sync.aligned.m8n8.x4.shared.b16 {%0,%1,%2,%3}, [%4];"
                 : "=r"(r[0]), "=r"(r[1]), "=r"(r[2]), "=r"(r[3]) : "r"(addr));
}
__device__ __forceinline__ void mma16816(float* c, const uint32_t* a, const uint32_t* b) {
    asm volatile(
        "mma.sync.aligned.m16n8k16.row.col.f32.bf16.bf16.f32 "
        "{%0,%1,%2,%3}, {%4,%5,%6,%7}, {%8,%9}, {%0,%1,%2,%3};"
        : "+f"(c[0]), "+f"(c[1]), "+f"(c[2]), "+f"(c[3])
        : "r"(a[0]), "r"(a[1]), "r"(a[2]), "r"(a[3]), "r"(b[0]), "r"(b[1]));
}
__device__ __forceinline__ void split2(float x, unsigned short& h, unsigned short& l) {
    __nv_bfloat16 hb = __float2bfloat16(x);
    float r = x - __bfloat162float(hb);
    __nv_bfloat16 lb = __float2bfloat16(r);
    h = *reinterpret_cast<unsigned short*>(&hb);
    l = *reinterpret_cast<unsigned short*>(&lb);
}
__device__ __forceinline__ void split_pack(float x, float y, uint32_t& hi, uint32_t& lo) {
    unsigned short hx, lx, hy, ly;
    split2(x, hx, lx); split2(y, hy, ly);
    hi = (uint32_t)hx | ((uint32_t)hy << 16);
    lo = (uint32_t)lx | ((uint32_t)ly << 16);
}
__device__ __forceinline__ float sigf(float v) { return 1.f / (1.f + __expf(-v)); }
__device__ __forceinline__ void grid_barrier() {
    __syncthreads();
    if (threadIdx.x == 0) {
        __threadfence();
        unsigned ticket = atomicAdd(&g_bar, 1u);
        unsigned target = (ticket & ~(unsigned)(NBLK - 1)) + NBLK;
        while ((int)(*(volatile unsigned*)&g_bar - target) < 0) { __nanosleep(20); }
        __threadfence();
    }
    __syncthreads();
}

// ============ weight pre-conversion: fp32 [k][n] -> bf16 hi/lo [n][k] ============
__global__ void convert_weights(const float* __restrict__ lin_w,
                                const float* __restrict__ g0w,
                                const float* __restrict__ g1w) {
    int t = blockIdx.x * blockDim.x + threadIdx.x;
    const float* src;
    int stride;
    __nv_bfloat16 *dh, *dl;
    if (t < 8 * 2048) {
        int cell = t >> 11, n = t & 2047;
        src = lin_w + (size_t)cell * 1024 * 2048 + n;
        stride = 2048;
        dh = d_linw_h + (size_t)t * 1024;
        dl = d_linw_l + (size_t)t * 1024;
    } else {
        int t2 = t - 8 * 2048;
        if (t2 >= 8 * 1024) return;
        int cell = t2 >> 10, n = t2 & 1023;
        src = (n < 512) ? (g0w + (size_t)cell * 1024 * 512 + n)
                        : (g1w + (size_t)cell * 1024 * 512 + (n - 512));
        stride = 512;
        dh = d_gw_h + (size_t)t2 * 1024;
        dl = d_gw_l + (size_t)t2 * 1024;
    }
    for (int k0 = 0; k0 < 1024; k0 += 8) {
        unsigned short hb[8], lb[8];
#pragma unroll
        for (int i = 0; i < 8; ++i)
            split2(src[(size_t)(k0 + i) * stride], hb[i], lb[i]);
        *(uint4*)(dh + k0) = *(uint4*)hb;
        *(uint4*)(dl + k0) = *(uint4*)lb;
    }
}

// ====== 4 k-steps of a resident chunk, 16x16 warp tile, 3-pass hi/lo ======
__device__ __forceinline__ void compute4(
    uint32_t base, uint32_t aOffH, uint32_t aOffL,
    uint32_t wOffH, uint32_t wOffL, float* acc)
{
#pragma unroll
    for (int s = 0; s < 4; ++s) {
        uint32_t ah[4], al[4], bh[4], bl[4];
        ldm_x4(ah, base + aOffH + s * 32);
        ldm_x4(al, base + aOffL + s * 32);
        ldm_x4(bh, base + wOffH + s * 32);
        ldm_x4(bl, base + wOffL + s * 32);
        mma16816(acc,     ah, bh);
        mma16816(acc + 4, ah, bh + 2);
        mma16816(acc,     al, bh);
        mma16816(acc + 4, al, bh + 2);
        mma16816(acc,     ah, bl);
        mma16816(acc + 4, ah, bl + 2);
    }
}

// ====== stage-1 GEMM: C[64 x 32], warps 4m x 2n x 2k, warp tile 16x16 ======
__device__ __forceinline__ void gemm_s1(
    uint32_t smb, char* smraw, int mbase, int nbase,
    const __nv_bfloat16* __restrict__ a0h, const __nv_bfloat16* __restrict__ a0l,
    const __nv_bfloat16* __restrict__ a1h, const __nv_bfloat16* __restrict__ a1l,
    const __nv_bfloat16* __restrict__ wh,  const __nv_bfloat16* __restrict__ wl)
{
    const int tid = threadIdx.x, lane = tid & 31, wid = tid >> 5;
    const int wm = wid & 3, wn = (wid >> 2) & 1, wk = wid >> 3;
    const int g = lane >> 2, tg = lane & 3;
    float acc[8];
#pragma unroll
    for (int i = 0; i < 8; ++i) acc[i] = 0.f;

    const uint32_t aOffH = (uint32_t)(wm * 16 + (lane & 15)) * S1_ROWB +
                           (lane >> 4) * 16 + wk * 128;
    const uint32_t aOffL = aOffH + S1_A_LO;
    const uint32_t wOffH = S1_W_HI +
                           (uint32_t)(wn * 16 + (lane & 7) + ((lane >> 4) & 1) * 8) *
                               S1_ROWB + ((lane >> 3) & 1) * 16 + wk * 128;
    const uint32_t wOffL = wOffH + (S1_W_LO - S1_W_HI);

    const int arow = tid >> 3, agr = (tid & 7) * 2;
    const int wrow = (tid >> 3) & 31, wgr = (tid & 7) * 2;

    auto issue = [&](int kc) {
        const uint32_t st = smb + (uint32_t)(kc % 3) * S1_SZ;
        const __nv_bfloat16* ah = (kc < 4) ? a0h : a1h;
        const __nv_bfloat16* al = (kc < 4) ? a0l : a1l;
        const int koff = (kc & 3) * 128;
        const __nv_bfloat16* srh = ah + (size_t)(mbase + arow) * 512 + koff + agr * 8;
        const __nv_bfloat16* srl = al + (size_t)(mbase + arow) * 512 + koff + agr * 8;
        const uint32_t dA = st + (uint32_t)arow * S1_ROWB + agr * 16;
        cpa16(dA, srh);            cpa16(dA + 16, srh + 8);
        cpa16(dA + S1_A_LO, srl);  cpa16(dA + S1_A_LO + 16, srl + 8);
        const __nv_bfloat16* wsrc = ((tid < 256) ? wh : wl) +
                                    (size_t)(nbase + wrow) * 1024 + kc * 128 + wgr * 8;
        const uint32_t dW = st + ((tid < 256) ? S1_W_HI : S1_W_LO) +
                            (uint32_t)wrow * S1_ROWB + wgr * 16;
        cpa16(dW, wsrc);  cpa16(dW + 16, wsrc + 8);
        cp_commit();
    };

    issue(0); issue(1);
    for (int kc = 0; kc < 8; ++kc) {
        if (kc < 7) cp_wait<1>(); else cp_wait<0>();
        __syncthreads();
        if (kc + 2 < 8) issue(kc + 2);
        compute4(smb + (uint32_t)(kc % 3) * S1_SZ, aOffH, aOffL, wOffH, wOffL, acc);
    }
    // publish partials: P[wk(2)][m(64)][n(32)]
    float* P = (float*)(smraw + P_OFF);
#pragma unroll
    for (int nt = 0; nt < 2; ++nt)
#pragma unroll
        for (int rr = 0; rr < 2; ++rr) {
            const int m = wm * 16 + rr * 8 + g;
            const int n = wn * 16 + nt * 8 + tg * 2;
            *(float2*)&P[(wk << 11) + m * 32 + n] =
                make_float2(acc[nt * 4 + rr * 2], acc[nt * 4 + rr * 2 + 1]);
        }
    __syncthreads();
}

// ====== stage-2 GEMM: C[32 x 32], warps 2m x 2n x 4k, warp tile 16x16 ======
__device__ __forceinline__ void gemm_s2(
    uint32_t smb, char* smraw, int mbase, int nbase,
    const __nv_bfloat16* __restrict__ s0h, const __nv_bfloat16* __restrict__ s0l,
    const __nv_bfloat16* __restrict__ s1h, const __nv_bfloat16* __restrict__ s1l,
    const __nv_bfloat16* __restrict__ wh,  const __nv_bfloat16* __restrict__ wl)
{
    const int tid = threadIdx.x, lane = tid & 31, wid = tid >> 5;
    const int wm = wid & 1, wn = (wid >> 1) & 1, wk = wid >> 2;
    const int g = lane >> 2, tg = lane & 3;
    float acc[8];
#pragma unroll
    for (int i = 0; i < 8; ++i) acc[i] = 0.f;

    const uint32_t aOffH = (uint32_t)(wm * 16 + (lane & 15)) * S2_ROWB +
                           (lane >> 4) * 16 + wk * 128;
    const uint32_t aOffL = aOffH + S2_A_LO;
    const uint32_t wOffH = S2_W_HI +
                           (uint32_t)(wn * 16 + (lane & 7) + ((lane >> 4) & 1) * 8) *
                               S2_ROWB + ((lane >> 3) & 1) * 16 + wk * 128;
    const uint32_t wOffL = wOffH + (S2_W_LO - S2_W_HI);

    const int arow = tid >> 4, agr = (tid & 15) * 2;
    const int wpl  = tid >> 8, wwrow = (tid & 255) >> 3, wgb = (tid & 7) * 4;

    auto issue = [&](int kc) {
        const uint32_t st = smb + (uint32_t)(kc % 3) * S2_SZ;
#pragma unroll
        for (int i = 0; i < 2; ++i) {
            int gidx = agr + i;
            const __nv_bfloat16* phh = (gidx < 16) ? s0h : s1h;
            const __nv_bfloat16* pll = (gidx < 16) ? s0l : s1l;
            int kk = kc * 128 + (gidx & 15) * 8;
            cpa16(st + (uint32_t)arow * S2_ROWB + gidx * 16,
                  phh + (size_t)(mbase + arow) * 512 + kk);
            cpa16(st + S2_A_LO + (uint32_t)arow * S2_ROWB + gidx * 16,
                  pll + (size_t)(mbase + arow) * 512 + kk);
        }
        const __nv_bfloat16* wp = wpl ? wl : wh;
        const uint32_t wdst = st + (wpl ? S2_W_LO : S2_W_HI) +
                              (uint32_t)wwrow * S2_ROWB;
#pragma unroll
        for (int i = 0; i < 4; ++i) {
            int gidx = wgb + i;
            int kk = (gidx < 16) ? (kc * 128 + gidx * 8)
                                 : (512 + kc * 128 + (gidx - 16) * 8);
            cpa16(wdst + gidx * 16, wp + (size_t)(nbase + wwrow) * 1024 + kk);
        }
        cp_commit();
    };

    issue(0); issue(1);
    for (int kc = 0; kc < 4; ++kc) {
        if (kc < 3) cp_wait<1>(); else cp_wait<0>();
        __syncthreads();
        if (kc + 2 < 4) issue(kc + 2);
        compute4(smb + (uint32_t)(kc % 3) * S2_SZ, aOffH, aOffL, wOffH, wOffL, acc);
    }
    // publish partials: P2[wk(4)][m(32)][n(32)] (slot-1 region, dead by now)
    float* P2 = (float*)(smraw + S2_SZ);
#pragma unroll
    for (int nt = 0; nt < 2; ++nt)
#pragma unroll
        for (int rr = 0; rr < 2; ++rr) {
            const int m = wm * 16 + rr * 8 + g;
            const int n = wn * 16 + nt * 8 + tg * 2;
            *(float2*)&P2[((wk << 5) + m) * 32 + n] =
                make_float2(acc[nt * 4 + rr * 2], acc[nt * 4 + rr * 2 + 1]);
        }
    __syncthreads();
}

// =================== main persistent kernel ===================
__global__ void __launch_bounds__(NTHR, 1) lattice_mma(
    const float* __restrict__ H0in,
    const float* __restrict__ lin_b,
    const float* __restrict__ g0b, const float* __restrict__ g1b,
    float* __restrict__ out)
{
    extern __shared__ __align__(16) char smraw[];
    const uint32_t smb = smem_u32(smraw);

    const int tid = threadIdx.x;
    const int blk = blockIdx.x;

    for (int i = tid + blk * NTHR; i < L_ * BH; i += NBLK * NTHR) {
        d_H1[0][i] = 0.f;
        d_H1h[0][i] = __float2bfloat16(0.f);
        d_H1l[0][i] = __float2bfloat16(0.f);
    }
    for (int e = tid + blk * NTHR; e < BH; e += NBLK * NTHR) {
        int b = e >> 9, h = e & (H_ - 1);
        float v = __ldg(&H0in[(size_t)b * T_ * H_ + h]);
        unsigned short hh, ll;
        split2(v, hh, ll);
        d_x0h[0][e] = *reinterpret_cast<__nv_bfloat16*>(&hh);
        d_x0l[0][e] = *reinterpret_cast<__nv_bfloat16*>(&ll);
    }
    grid_barrier();

    float* out_h1 = out + (size_t)B_ * T_ * H_;

    const int m1base = (blk & 1) * 64, n1base = (blk >> 1) * 32;
    const int m2base = (blk & 3) * 32, n2base = (blk >> 2) * 32;
    const bool g0side = (n2base < 512);
    const int region = n1base >> 9;            // 0,1: z   2: r   3: q

    const int e1m = tid >> 3, e1n = (tid & 7) * 4;   // stage-1 coop epilogue 64x32
    const int e2m = tid >> 4, e2n = (tid & 15) * 2;  // stage-2 coop epilogue 32x32

    for (int s = 0; s < T_ + L_ - 1; ++s) {
        const int par = s & 1;
        for (int jj = 0; jj < J_; ++jj) {
            // =============== stage 1: all active layers ===============
            for (int l = 0; l < L_; ++l) {
                const int t = s - l;
                if (t < 0 || t >= T_) continue;
                const int cell = l * J_ + jj;

                const float* h0src;
                int lda0;
                const __nv_bfloat16 *h0sh, *h0sl, *h1sh, *h1sl;
                const float* h1src;
                if (jj == 0) {
                    h1src = d_H1[l];
                    h1sh = d_H1h[l]; h1sl = d_H1l[l];
                    if (l == 0) {
                        h0src = H0in + (size_t)t * H_;  lda0 = T_ * H_;
                        h0sh = d_x0h[par];  h0sl = d_x0l[par];
                    } else {
                        h0src = d_h0out[par ^ 1][l - 1];  lda0 = H_;
                        h0sh = d_h0outh[par ^ 1][l - 1];
                        h0sl = d_h0outl[par ^ 1][l - 1];
                    }
                } else {
                    h0src = d_h0mid[l];  lda0 = H_;
                    h0sh = d_h0midh[l];  h0sl = d_h0midl[l];
                    h1src = d_h1mid[l];
                    h1sh = d_h1midh[l];  h1sl = d_h1midl[l];
                }

                gemm_s1(smb, smraw, m1base, n1base,
                        h0sh, h0sl, h1sh, h1sl,
                        d_linw_h + (size_t)cell * 2048 * 1024,
                        d_linw_l + (size_t)cell * 2048 * 1024);

                // cooperative epilogue
                const float* P = (const float*)(smraw + P_OFF);
                float4 p0 = *(const float4*)&P[e1m * 32 + e1n];
                float4 p1 = *(const float4*)&P[2048 + e1m * 32 + e1n];
                const int   mrow = m1base + e1m;
                const int   col  = n1base + e1n;
                const float* bp  = lin_b + (size_t)cell * 2048 + col;
                const float s0 = sigf(p0.x + p1.x + bp[0]);
                const float s1 = sigf(p0.y + p1.y + bp[1]);
                const float s2 = sigf(p0.z + p1.z + bp[2]);
                const float s3 = sigf(p0.w + p1.w + bp[3]);
                if (region < 2) {
                    *(float4*)&d_zL[l][mrow * 1024 + col] =
                        make_float4(s0, s1, s2, s3);
                } else if (region == 2) {
                    const int cc = col - 1024;
                    float4 h = __ldcg((const float4*)&h1src[mrow * H_ + cc]);
                    uint32_t h01, l01, h23, l23;
                    split_pack(s0 * h.x, s1 * h.y, h01, l01);
                    split_pack(s2 * h.z, s3 * h.w, h23, l23);
                    *(uint2*)&d_arh[l][mrow * H_ + cc] = make_uint2(h01, h23);
                    *(uint2*)&d_arl[l][mrow * H_ + cc] = make_uint2(l01, l23);
                } else {
                    const int cc = col - 1536;
                    float4 h = __ldcg((const float4*)&h0src[(size_t)mrow * lda0 + cc]);
                    uint32_t h01, l01, h23, l23;
                    split_pack(s0 * h.x, s1 * h.y, h01, l01);
                    split_pack(s2 * h.z, s3 * h.w, h23, l23);
                    *(uint2*)&d_aqh[l][mrow * H_ + cc] = make_uint2(h01, h23);
                    *(uint2*)&d_aql[l][mrow * H_ + cc] = make_uint2(l01, l23);
                }
                __syncthreads();
            }
            grid_barrier();

            // =============== stage 2: all active layers ===============
            for (int l = 0; l < L_; ++l) {
                const int t = s - l;
                if (t < 0 || t >= T_) continue;
                const int  cell = l * J_ + jj;
                const bool last = (jj == 1) && (l == L_ - 1);

                const float* h0src;
                int lda0;
                const __nv_bfloat16 *h0sh, *h0sl, *h1sh, *h1sl;
                const float* h1src;
                if (jj == 0) {
                    h1src = d_H1[l];
                    h1sh = d_H1h[l]; h1sl = d_H1l[l];
                    if (l == 0) {
                        h0src = H0in + (size_t)t * H_;  lda0 = T_ * H_;
                        h0sh = d_x0h[par];  h0sl = d_x0l[par];
                    } else {
                        h0src = d_h0out[par ^ 1][l - 1];  lda0 = H_;
                        h0sh = d_h0outh[par ^ 1][l - 1];
                        h0sl = d_h0outl[par ^ 1][l - 1];
                    }
                } else {
                    h0src = d_h0mid[l];  lda0 = H_;
                    h0sh = d_h0midh[l];  h0sl = d_h0midl[l];
                    h1src = d_h1mid[l];
                    h1sh = d_h1midh[l];  h1sl = d_h1midl[l];
                }

                const __nv_bfloat16* a0h = g0side ? h0sh : h1sh;
                const __nv_bfloat16* a0l = g0side ? h0sl : h1sl;
                const __nv_bfloat16* a1h = g0side ? d_arh[l] : d_aqh[l];
                const __nv_bfloat16* a1l = g0side ? d_arl[l] : d_aql[l];
                gemm_s2(smb, smraw, m2base, n2base,
                        a0h, a0l, a1h, a1l,
                        d_gw_h + (size_t)cell * 1024 * 1024,
                        d_gw_l + (size_t)cell * 1024 * 1024);

                const float* P2 = (const float*)(smraw + S2_SZ);
                float2 q0 = *(const float2*)&P2[e2m * 32 + e2n];
                float2 q1 = *(const float2*)&P2[1024 + e2m * 32 + e2n];
                float2 q2 = *(const float2*)&P2[2048 + e2m * 32 + e2n];
                float2 q3 = *(const float2*)&P2[3072 + e2m * 32 + e2n];
                const float v0 = q0.x + q1.x + q2.x + q3.x;
                const float v1 = q0.y + q1.y + q2.y + q3.y;
                const int mrow = m2base + e2m;
                const int col  = n2base + e2n;
                if (g0side) {
                    float* h1dst = (jj == 1) ? d_H1[l] : d_h1mid[l];
                    __nv_bfloat16* h1dh = (jj == 1) ? d_H1h[l] : d_h1midh[l];
                    __nv_bfloat16* h1dl = (jj == 1) ? d_H1l[l] : d_h1midl[l];
                    const float* bp = g0b + (size_t)cell * H_ + col;
                    const float c0 = tanhf(v0 + bp[0]);
                    const float c1 = tanhf(v1 + bp[1]);
                    float2 z = __ldcg((const float2*)&d_zL[l][mrow * 1024 + H_ + col]);
                    float2 o = __ldcg((const float2*)&h1src[mrow * H_ + col]);
                    const float n0v = z.x * c0 + (1.f - z.x) * o.x;
                    const float n1v = z.y * c1 + (1.f - z.y) * o.y;
                    *(float2*)&h1dst[mrow * H_ + col] = make_float2(n0v, n1v);
                    uint32_t hi, lo;
                    split_pack(n0v, n1v, hi, lo);
                    *(uint32_t*)&h1dh[mrow * H_ + col] = hi;
                    *(uint32_t*)&h1dl[mrow * H_ + col] = lo;
                } else {
                    const int n2 = col - 512;
                    float* h0dst = last ? (out + (size_t)t * H_)
                                        : ((jj == 1) ? d_h0out[par][l] : d_h0mid[l]);
                    const int ldh0d = last ? (T_ * H_) : H_;
                    const float* bp = g1b + (size_t)cell * H_ + n2;
                    const float c0 = tanhf(v0 + bp[0]);
                    const float c1 = tanhf(v1 + bp[1]);
                    float2 z = __ldcg((const float2*)&d_zL[l][mrow * 1024 + n2]);
                    float2 o = __ldcg((const float2*)&h0src[(size_t)mrow * lda0 + n2]);
                    const float n0v = z.x * c0 + (1.f - z.x) * o.x;
                    const float n1v = z.y * c1 + (1.f - z.y) * o.y;
                    *(float2*)&h0dst[(size_t)mrow * ldh0d + n2] = make_float2(n0v, n1v);
                    if (!last) {
                        __nv_bfloat16* h0dh = (jj == 1) ? d_h0outh[par][l]
                                                        : d_h0midh[l];
                        __nv_bfloat16* h0dl = (jj == 1) ? d_h0outl[par][l]
                                                        : d_h0midl[l];
                        uint32_t hi, lo;
                        split_pack(n0v, n1v, hi, lo);
                        *(uint32_t*)&h0dh[mrow * H_ + n2] = hi;
                        *(uint32_t*)&h0dl[mrow * H_ + n2] = lo;
                    }
                }
                __syncthreads();
            }

            // prepare next step's input split (read-only source; safe anytime)
            if (jj == 1 && s + 1 < T_) {
                const int np = (s + 1) & 1;
                for (int e = tid + blk * NTHR; e < BH; e += NBLK * NTHR) {
                    int b = e >> 9, h = e & (H_ - 1);
                    float v = __ldg(&H0in[((size_t)b * T_ + (s + 1)) * H_ + h]);
                    unsigned short hh, ll;
                    split2(v, hh, ll);
                    d_x0h[np][e] = *reinterpret_cast<__nv_bfloat16*>(&hh);
                    d_x0l[np][e] = *reinterpret_cast<__nv_bfloat16*>(&ll);
                }
            }
            grid_barrier();
        }
    }

    // H1_final: out2[b, l, h] = d_H1[l][b*H + h]
    for (int i = tid + blk * NTHR; i < L_ * BH; i += NBLK * NTHR) {
        int h    = i & (H_ - 1);
        int rest = i >> 9;
        int b    = rest & (B_ - 1);
        int l    = rest >> 7;
        out_h1[((size_t)b * L_ + l) * H_ + h] = __ldcg(&d_H1[0][i]);
    }
}

extern "C" void kernel_launch(void* const* d_in, const int* in_sizes, int n_in,
                              void* d_out, int out_size)
{
    const float* H0in  = (const float*)d_in[0];
    const float* lin_w = (const float*)d_in[1];
    const float* lin_b = (const float*)d_in[2];
    const float* g0w   = (const float*)d_in[3];
    const float* g0b   = (const float*)d_in[4];
    const float* g1w   = (const float*)d_in[5];
    const float* g1b   = (const float*)d_in[6];

    cudaFuncSetAttribute(lattice_mma,
                         cudaFuncAttributeMaxDynamicSharedMemorySize, SMEM_TOTAL);

    convert_weights<<<96, 256>>>(lin_w, g0w, g1w);
    lattice_mma<<<NBLK, NTHR, SMEM_TOTAL>>>(H0in, lin_b, g0b, g1b, (float*)d_out);
}

// round 16
// speedup vs baseline: 1.5545x; 1.3536x over previous
#include <cuda_runtime.h>
#include <cuda_fp16.h>
#include <cstdint>

#define H_    512
#define B_    128
#define T_    512
#define L_    4
#define J_    2
#define NBLK  128
#define NTHR  512
#define BH    (B_ * H_)

// ---- stage-1 smem slot (3-slot ring): Ah 64x128k, Al, Wh 32x128k ----
#define S1_ROWB 272
#define S1_A_LO 17408
#define S1_W_HI 34816
#define S1_SZ   43520
// ---- stage-2 smem slot (3-slot ring): Ah 32x(2x128k), Al, Wh 32x(2x128k) ----
#define S2_ROWB 528
#define S2_A_LO 16896
#define S2_W_HI 33792
#define S2_SZ   50688
#define P_OFF   130560               // 3*S1_SZ: stage-1 partial scratch (16KB)
#define SMEM_TOTAL (3 * S2_SZ)       // 152064

// ---- converted weights (fp16, transposed to [n][k]) ----
__device__ __half d_linw[8u * 2048u * 1024u];
__device__ __half d_gw[8u * 1024u * 1024u];    // n<512: g0w, n>=512: g1w

// ---- per-layer wavefront state ----
__device__ __align__(128) float d_zL[L_][B_ * 1024];
__device__ __align__(128) float d_h0mid[L_][BH], d_h1mid[L_][BH];
__device__ __align__(128) float d_h0out[2][L_][BH];
__device__ __align__(128) float d_H1[L_][BH];
__device__ __align__(128) __half d_h0midh[L_][BH], d_h0midl[L_][BH];
__device__ __align__(128) __half d_h1midh[L_][BH], d_h1midl[L_][BH];
__device__ __align__(128) __half d_h0outh[2][L_][BH], d_h0outl[2][L_][BH];
__device__ __align__(128) __half d_H1h[L_][BH], d_H1l[L_][BH];
__device__ __align__(128) __half d_x0h[2][BH], d_x0l[2][BH];
__device__ __align__(128) __half d_arh[L_][BH], d_arl[L_][BH];
__device__ __align__(128) __half d_aqh[L_][BH], d_aql[L_][BH];
__device__ unsigned int g_bar = 0;

// ================= helpers =================
__device__ __forceinline__ uint32_t smem_u32(const void* p) {
    uint32_t a;
    asm("{ .reg .u64 t; cvta.to.shared.u64 t, %1; cvt.u32.u64 %0, t; }"
        : "=r"(a) : "l"(p));
    return a;
}
__device__ __forceinline__ void cpa16(uint32_t d, const void* s) {
    asm volatile("cp.async.cg.shared.global [%0], [%1], 16;" :: "r"(d), "l"(s));
}
__device__ __forceinline__ void cp_commit() {
    asm volatile("cp.async.commit_group;" ::: "memory");
}
template <int N>
__device__ __forceinline__ void cp_wait() {
    asm volatile("cp.async.wait_group %0;" :: "n"(N) : "memory");
}
__device__ __forceinline__ void ldm_x4(uint32_t* r, uint32_t addr) {
    asm volatile("ldmatrix.sync.aligned.m8n8.x4.shared.b16 {%0,%1,%2,%3}, [%4];"
                 : "=r"(r[0]), "=r"(r[1]), "=r"(r[2]), "=r"(r[3]) : "r"(addr));
}
__device__ __forceinline__ void mma16816(float* c, const uint32_t* a, const uint32_t* b) {
    asm volatile(
        "mma.sync.aligned.m16n8k16.row.col.f32.f16.f16.f32 "
        "{%0,%1,%2,%3}, {%4,%5,%6,%7}, {%8,%9}, {%0,%1,%2,%3};"
        : "+f"(c[0]), "+f"(c[1]), "+f"(c[2]), "+f"(c[3])
        : "r"(a[0]), "r"(a[1]), "r"(a[2]), "r"(a[3]), "r"(b[0]), "r"(b[1]));
}
__device__ __forceinline__ void split2(float x, unsigned short& h, unsigned short& l) {
    __half hb = __float2half(x);
    float r = x - __half2float(hb);
    __half lb = __float2half(r);
    h = *reinterpret_cast<unsigned short*>(&hb);
    l = *reinterpret_cast<unsigned short*>(&lb);
}
__device__ __forceinline__ void split_pack(float x, float y, uint32_t& hi, uint32_t& lo) {
    unsigned short hx, lx, hy, ly;
    split2(x, hx, lx); split2(y, hy, ly);
    hi = (uint32_t)hx | ((uint32_t)hy << 16);
    lo = (uint32_t)lx | ((uint32_t)ly << 16);
}
__device__ __forceinline__ float sigf(float v) { return 1.f / (1.f + __expf(-v)); }
__device__ __forceinline__ void grid_barrier() {
    __syncthreads();
    if (threadIdx.x == 0) {
        __threadfence();
        unsigned ticket = atomicAdd(&g_bar, 1u);
        unsigned target = (ticket & ~(unsigned)(NBLK - 1)) + NBLK;
        while ((int)(*(volatile unsigned*)&g_bar - target) < 0) { __nanosleep(20); }
        __threadfence();
    }
    __syncthreads();
}

// ============ weight pre-conversion: fp32 [k][n] -> fp16 [n][k] ============
__global__ void convert_weights(const float* __restrict__ lin_w,
                                const float* __restrict__ g0w,
                                const float* __restrict__ g1w) {
    int t = blockIdx.x * blockDim.x + threadIdx.x;
    const float* src;
    int stride;
    __half* dh;
    if (t < 8 * 2048) {
        int cell = t >> 11, n = t & 2047;
        src = lin_w + (size_t)cell * 1024 * 2048 + n;
        stride = 2048;
        dh = d_linw + (size_t)t * 1024;
    } else {
        int t2 = t - 8 * 2048;
        if (t2 >= 8 * 1024) return;
        int cell = t2 >> 10, n = t2 & 1023;
        src = (n < 512) ? (g0w + (size_t)cell * 1024 * 512 + n)
                        : (g1w + (size_t)cell * 1024 * 512 + (n - 512));
        stride = 512;
        dh = d_gw + (size_t)t2 * 1024;
    }
    for (int k0 = 0; k0 < 1024; k0 += 8) {
        unsigned short hb[8];
#pragma unroll
        for (int i = 0; i < 8; ++i) {
            __half v = __float2half(src[(size_t)(k0 + i) * stride]);
            hb[i] = *reinterpret_cast<unsigned short*>(&v);
        }
        *(uint4*)(dh + k0) = *(uint4*)hb;
    }
}

// ====== 4 k-steps of a resident chunk, 16x16 warp tile, fp16 2-pass ======
__device__ __forceinline__ void compute4(
    uint32_t base, uint32_t aOffH, uint32_t aOffL, uint32_t wOffH, float* acc)
{
#pragma unroll
    for (int s = 0; s < 4; ++s) {
        uint32_t ah[4], al[4], bh[4];
        ldm_x4(ah, base + aOffH + s * 32);
        ldm_x4(al, base + aOffL + s * 32);
        ldm_x4(bh, base + wOffH + s * 32);
        mma16816(acc,     ah, bh);
        mma16816(acc + 4, ah, bh + 2);
        mma16816(acc,     al, bh);
        mma16816(acc + 4, al, bh + 2);
    }
}

// ====== stage-1 GEMM: C[64 x 32], warps 4m x 2n x 2k, warp tile 16x16 ======
__device__ __forceinline__ void gemm_s1(
    uint32_t smb, char* smraw, int mbase, int nbase,
    const __half* __restrict__ a0h, const __half* __restrict__ a0l,
    const __half* __restrict__ a1h, const __half* __restrict__ a1l,
    const __half* __restrict__ wh)
{
    const int tid = threadIdx.x, lane = tid & 31, wid = tid >> 5;
    const int wm = wid & 3, wn = (wid >> 2) & 1, wk = wid >> 3;
    const int g = lane >> 2, tg = lane & 3;
    float acc[8];
#pragma unroll
    for (int i = 0; i < 8; ++i) acc[i] = 0.f;

    const uint32_t aOffH = (uint32_t)(wm * 16 + (lane & 15)) * S1_ROWB +
                           (lane >> 4) * 16 + wk * 128;
    const uint32_t aOffL = aOffH + S1_A_LO;
    const uint32_t wOffH = S1_W_HI +
                           (uint32_t)(wn * 16 + (lane & 7) + ((lane >> 4) & 1) * 8) *
                               S1_ROWB + ((lane >> 3) & 1) * 16 + wk * 128;

    const int arow = tid >> 3, agr = (tid & 7) * 2;
    const int wrow = tid >> 4, wgr = tid & 15;

    auto issue = [&](int kc) {
        const uint32_t st = smb + (uint32_t)(kc % 3) * S1_SZ;
        const __half* ah = (kc < 4) ? a0h : a1h;
        const __half* al = (kc < 4) ? a0l : a1l;
        const int koff = (kc & 3) * 128;
        const __half* srh = ah + (size_t)(mbase + arow) * 512 + koff + agr * 8;
        const __half* srl = al + (size_t)(mbase + arow) * 512 + koff + agr * 8;
        const uint32_t dA = st + (uint32_t)arow * S1_ROWB + agr * 16;
        cpa16(dA, srh);            cpa16(dA + 16, srh + 8);
        cpa16(dA + S1_A_LO, srl);  cpa16(dA + S1_A_LO + 16, srl + 8);
        cpa16(st + S1_W_HI + (uint32_t)wrow * S1_ROWB + wgr * 16,
              wh + (size_t)(nbase + wrow) * 1024 + kc * 128 + wgr * 8);
        cp_commit();
    };

    issue(0); issue(1);
    for (int kc = 0; kc < 8; ++kc) {
        if (kc < 7) cp_wait<1>(); else cp_wait<0>();
        __syncthreads();
        if (kc + 2 < 8) issue(kc + 2);
        compute4(smb + (uint32_t)(kc % 3) * S1_SZ, aOffH, aOffL, wOffH, acc);
    }
    // publish partials: P[wk(2)][m(64)][n(32)]
    float* P = (float*)(smraw + P_OFF);
#pragma unroll
    for (int nt = 0; nt < 2; ++nt)
#pragma unroll
        for (int rr = 0; rr < 2; ++rr) {
            const int m = wm * 16 + rr * 8 + g;
            const int n = wn * 16 + nt * 8 + tg * 2;
            *(float2*)&P[(wk << 11) + m * 32 + n] =
                make_float2(acc[nt * 4 + rr * 2], acc[nt * 4 + rr * 2 + 1]);
        }
    __syncthreads();
}

// ====== stage-2 GEMM: C[32 x 32], warps 2m x 2n x 4k, warp tile 16x16 ======
__device__ __forceinline__ void gemm_s2(
    uint32_t smb, char* smraw, int mbase, int nbase,
    const __half* __restrict__ s0h, const __half* __restrict__ s0l,
    const __half* __restrict__ s1h, const __half* __restrict__ s1l,
    const __half* __restrict__ wh)
{
    const int tid = threadIdx.x, lane = tid & 31, wid = tid >> 5;
    const int wm = wid & 1, wn = (wid >> 1) & 1, wk = wid >> 2;
    const int g = lane >> 2, tg = lane & 3;
    float acc[8];
#pragma unroll
    for (int i = 0; i < 8; ++i) acc[i] = 0.f;

    const uint32_t aOffH = (uint32_t)(wm * 16 + (lane & 15)) * S2_ROWB +
                           (lane >> 4) * 16 + wk * 128;
    const uint32_t aOffL = aOffH + S2_A_LO;
    const uint32_t wOffH = S2_W_HI +
                           (uint32_t)(wn * 16 + (lane & 7) + ((lane >> 4) & 1) * 8) *
                               S2_ROWB + ((lane >> 3) & 1) * 16 + wk * 128;

    const int arow = tid >> 4, agr = (tid & 15) * 2;
    const int wwrow = tid >> 4, wgb = (tid & 15) * 2;

    auto issue = [&](int kc) {
        const uint32_t st = smb + (uint32_t)(kc % 3) * S2_SZ;
#pragma unroll
        for (int i = 0; i < 2; ++i) {
            int gidx = agr + i;
            const __half* phh = (gidx < 16) ? s0h : s1h;
            const __half* pll = (gidx < 16) ? s0l : s1l;
            int kk = kc * 128 + (gidx & 15) * 8;
            cpa16(st + (uint32_t)arow * S2_ROWB + gidx * 16,
                  phh + (size_t)(mbase + arow) * 512 + kk);
            cpa16(st + S2_A_LO + (uint32_t)arow * S2_ROWB + gidx * 16,
                  pll + (size_t)(mbase + arow) * 512 + kk);
        }
        const uint32_t wdst = st + S2_W_HI + (uint32_t)wwrow * S2_ROWB;
#pragma unroll
        for (int i = 0; i < 2; ++i) {
            int gidx = wgb + i;
            int kk = (gidx < 16) ? (kc * 128 + gidx * 8)
                                 : (512 + kc * 128 + (gidx - 16) * 8);
            cpa16(wdst + gidx * 16, wh + (size_t)(nbase + wwrow) * 1024 + kk);
        }
        cp_commit();
    };

    issue(0); issue(1);
    for (int kc = 0; kc < 4; ++kc) {
        if (kc < 3) cp_wait<1>(); else cp_wait<0>();
        __syncthreads();
        if (kc + 2 < 4) issue(kc + 2);
        compute4(smb + (uint32_t)(kc % 3) * S2_SZ, aOffH, aOffL, wOffH, acc);
    }
    // publish partials: P2[wk(4)][m(32)][n(32)] (slot-1 region, dead by now)
    float* P2 = (float*)(smraw + S2_SZ);
#pragma unroll
    for (int nt = 0; nt < 2; ++nt)
#pragma unroll
        for (int rr = 0; rr < 2; ++rr) {
            const int m = wm * 16 + rr * 8 + g;
            const int n = wn * 16 + nt * 8 + tg * 2;
            *(float2*)&P2[((wk << 5) + m) * 32 + n] =
                make_float2(acc[nt * 4 + rr * 2], acc[nt * 4 + rr * 2 + 1]);
        }
    __syncthreads();
}

// =================== main persistent kernel ===================
__global__ void __launch_bounds__(NTHR, 1) lattice_mma(
    const float* __restrict__ H0in,
    const float* __restrict__ lin_b,
    const float* __restrict__ g0b, const float* __restrict__ g1b,
    float* __restrict__ out)
{
    extern __shared__ __align__(16) char smraw[];
    const uint32_t smb = smem_u32(smraw);

    const int tid = threadIdx.x;
    const int blk = blockIdx.x;

    for (int i = tid + blk * NTHR; i < L_ * BH; i += NBLK * NTHR) {
        d_H1[0][i] = 0.f;
        d_H1h[0][i] = __float2half(0.f);
        d_H1l[0][i] = __float2half(0.f);
    }
    for (int e = tid + blk * NTHR; e < BH; e += NBLK * NTHR) {
        int b = e >> 9, h = e & (H_ - 1);
        float v = __ldg(&H0in[(size_t)b * T_ * H_ + h]);
        unsigned short hh, ll;
        split2(v, hh, ll);
        d_x0h[0][e] = *reinterpret_cast<__half*>(&hh);
        d_x0l[0][e] = *reinterpret_cast<__half*>(&ll);
    }
    grid_barrier();

    float* out_h1 = out + (size_t)B_ * T_ * H_;

    const int m1base = (blk & 1) * 64, n1base = (blk >> 1) * 32;
    const int m2base = (blk & 3) * 32, n2base = (blk >> 2) * 32;
    const bool g0side = (n2base < 512);
    const int region = n1base >> 9;            // 0,1: z   2: r   3: q

    const int e1m = tid >> 3, e1n = (tid & 7) * 4;
    const int e2m = tid >> 4, e2n = (tid & 15) * 2;

    for (int s = 0; s < T_ + L_ - 1; ++s) {
        const int par = s & 1;
        for (int jj = 0; jj < J_; ++jj) {
            // =============== stage 1: all active layers ===============
            for (int l = 0; l < L_; ++l) {
                const int t = s - l;
                if (t < 0 || t >= T_) continue;
                const int cell = l * J_ + jj;

                const float* h0src;
                int lda0;
                const __half *h0sh, *h0sl, *h1sh, *h1sl;
                const float* h1src;
                if (jj == 0) {
                    h1src = d_H1[l];
                    h1sh = d_H1h[l]; h1sl = d_H1l[l];
                    if (l == 0) {
                        h0src = H0in + (size_t)t * H_;  lda0 = T_ * H_;
                        h0sh = d_x0h[par];  h0sl = d_x0l[par];
                    } else {
                        h0src = d_h0out[par ^ 1][l - 1];  lda0 = H_;
                        h0sh = d_h0outh[par ^ 1][l - 1];
                        h0sl = d_h0outl[par ^ 1][l - 1];
                    }
                } else {
                    h0src = d_h0mid[l];  lda0 = H_;
                    h0sh = d_h0midh[l];  h0sl = d_h0midl[l];
                    h1src = d_h1mid[l];
                    h1sh = d_h1midh[l];  h1sl = d_h1midl[l];
                }

                gemm_s1(smb, smraw, m1base, n1base,
                        h0sh, h0sl, h1sh, h1sl,
                        d_linw + (size_t)cell * 2048 * 1024);

                const float* P = (const float*)(smraw + P_OFF);
                float4 p0 = *(const float4*)&P[e1m * 32 + e1n];
                float4 p1 = *(const float4*)&P[2048 + e1m * 32 + e1n];
                const int   mrow = m1base + e1m;
                const int   col  = n1base + e1n;
                const float* bp  = lin_b + (size_t)cell * 2048 + col;
                const float s0 = sigf(p0.x + p1.x + bp[0]);
                const float s1 = sigf(p0.y + p1.y + bp[1]);
                const float s2 = sigf(p0.z + p1.z + bp[2]);
                const float s3 = sigf(p0.w + p1.w + bp[3]);
                if (region < 2) {
                    *(float4*)&d_zL[l][mrow * 1024 + col] =
                        make_float4(s0, s1, s2, s3);
                } else if (region == 2) {
                    const int cc = col - 1024;
                    float4 h = __ldcg((const float4*)&h1src[mrow * H_ + cc]);
                    uint32_t h01, l01, h23, l23;
                    split_pack(s0 * h.x, s1 * h.y, h01, l01);
                    split_pack(s2 * h.z, s3 * h.w, h23, l23);
                    *(uint2*)&d_arh[l][mrow * H_ + cc] = make_uint2(h01, h23);
                    *(uint2*)&d_arl[l][mrow * H_ + cc] = make_uint2(l01, l23);
                } else {
                    const int cc = col - 1536;
                    float4 h = __ldcg((const float4*)&h0src[(size_t)mrow * lda0 + cc]);
                    uint32_t h01, l01, h23, l23;
                    split_pack(s0 * h.x, s1 * h.y, h01, l01);
                    split_pack(s2 * h.z, s3 * h.w, h23, l23);
                    *(uint2*)&d_aqh[l][mrow * H_ + cc] = make_uint2(h01, h23);
                    *(uint2*)&d_aql[l][mrow * H_ + cc] = make_uint2(l01, l23);
                }
                __syncthreads();
            }
            grid_barrier();

            // =============== stage 2: all active layers ===============
            for (int l = 0; l < L_; ++l) {
                const int t = s - l;
                if (t < 0 || t >= T_) continue;
                const int  cell = l * J_ + jj;
                const bool last = (jj == 1) && (l == L_ - 1);

                const float* h0src;
                int lda0;
                const __half *h0sh, *h0sl, *h1sh, *h1sl;
                const float* h1src;
                if (jj == 0) {
                    h1src = d_H1[l];
                    h1sh = d_H1h[l]; h1sl = d_H1l[l];
                    if (l == 0) {
                        h0src = H0in + (size_t)t * H_;  lda0 = T_ * H_;
                        h0sh = d_x0h[par];  h0sl = d_x0l[par];
                    } else {
                        h0src = d_h0out[par ^ 1][l - 1];  lda0 = H_;
                        h0sh = d_h0outh[par ^ 1][l - 1];
                        h0sl = d_h0outl[par ^ 1][l - 1];
                    }
                } else {
                    h0src = d_h0mid[l];  lda0 = H_;
                    h0sh = d_h0midh[l];  h0sl = d_h0midl[l];
                    h1src = d_h1mid[l];
                    h1sh = d_h1midh[l];  h1sl = d_h1midl[l];
                }

                const __half* a0h = g0side ? h0sh : h1sh;
                const __half* a0l = g0side ? h0sl : h1sl;
                const __half* a1h = g0side ? d_arh[l] : d_aqh[l];
                const __half* a1l = g0side ? d_arl[l] : d_aql[l];
                gemm_s2(smb, smraw, m2base, n2base,
                        a0h, a0l, a1h, a1l,
                        d_gw + (size_t)cell * 1024 * 1024);

                const float* P2 = (const float*)(smraw + S2_SZ);
                float2 q0 = *(const float2*)&P2[e2m * 32 + e2n];
                float2 q1 = *(const float2*)&P2[1024 + e2m * 32 + e2n];
                float2 q2 = *(const float2*)&P2[2048 + e2m * 32 + e2n];
                float2 q3 = *(const float2*)&P2[3072 + e2m * 32 + e2n];
                const float v0 = q0.x + q1.x + q2.x + q3.x;
                const float v1 = q0.y + q1.y + q2.y + q3.y;
                const int mrow = m2base + e2m;
                const int col  = n2base + e2n;
                if (g0side) {
                    float* h1dst = (jj == 1) ? d_H1[l] : d_h1mid[l];
                    __half* h1dh = (jj == 1) ? d_H1h[l] : d_h1midh[l];
                    __half* h1dl = (jj == 1) ? d_H1l[l] : d_h1midl[l];
                    const float* bp = g0b + (size_t)cell * H_ + col;
                    const float c0 = tanhf(v0 + bp[0]);
                    const float c1 = tanhf(v1 + bp[1]);
                    float2 z = __ldcg((const float2*)&d_zL[l][mrow * 1024 + H_ + col]);
                    float2 o = __ldcg((const float2*)&h1src[mrow * H_ + col]);
                    const float n0v = z.x * c0 + (1.f - z.x) * o.x;
                    const float n1v = z.y * c1 + (1.f - z.y) * o.y;
                    *(float2*)&h1dst[mrow * H_ + col] = make_float2(n0v, n1v);
                    uint32_t hi, lo;
                    split_pack(n0v, n1v, hi, lo);
                    *(uint32_t*)&h1dh[mrow * H_ + col] = hi;
                    *(uint32_t*)&h1dl[mrow * H_ + col] = lo;
                } else {
                    const int n2 = col - 512;
                    float* h0dst = last ? (out + (size_t)t * H_)
                                        : ((jj == 1) ? d_h0out[par][l] : d_h0mid[l]);
                    const int ldh0d = last ? (T_ * H_) : H_;
                    const float* bp = g1b + (size_t)cell * H_ + n2;
                    const float c0 = tanhf(v0 + bp[0]);
                    const float c1 = tanhf(v1 + bp[1]);
                    float2 z = __ldcg((const float2*)&d_zL[l][mrow * 1024 + n2]);
                    float2 o = __ldcg((const float2*)&h0src[(size_t)mrow * lda0 + n2]);
                    const float n0v = z.x * c0 + (1.f - z.x) * o.x;
                    const float n1v = z.y * c1 + (1.f - z.y) * o.y;
                    *(float2*)&h0dst[(size_t)mrow * ldh0d + n2] = make_float2(n0v, n1v);
                    if (!last) {
                        __half* h0dh = (jj == 1) ? d_h0outh[par][l] : d_h0midh[l];
                        __half* h0dl = (jj == 1) ? d_h0outl[par][l] : d_h0midl[l];
                        uint32_t hi, lo;
                        split_pack(n0v, n1v, hi, lo);
                        *(uint32_t*)&h0dh[mrow * H_ + n2] = hi;
                        *(uint32_t*)&h0dl[mrow * H_ + n2] = lo;
                    }
                }
                __syncthreads();
            }

            // prepare next step's input split
            if (jj == 1 && s + 1 < T_) {
                const int np = (s + 1) & 1;
                for (int e = tid + blk * NTHR; e < BH; e += NBLK * NTHR) {
                    int b = e >> 9, h = e & (H_ - 1);
                    float v = __ldg(&H0in[((size_t)b * T_ + (s + 1)) * H_ + h]);
                    unsigned short hh, ll;
                    split2(v, hh, ll);
                    d_x0h[np][e] = *reinterpret_cast<__half*>(&hh);
                    d_x0l[np][e] = *reinterpret_cast<__half*>(&ll);
                }
            }
            grid_barrier();
        }
    }

    // H1_final: out2[b, l, h] = d_H1[l][b*H + h]
    for (int i = tid + blk * NTHR; i < L_ * BH; i += NBLK * NTHR) {
        int h    = i & (H_ - 1);
        int rest = i >> 9;
        int b    = rest & (B_ - 1);
        int l    = rest >> 7;
        out_h1[((size_t)b * L_ + l) * H_ + h] = __ldcg(&d_H1[0][i]);
    }
}

extern "C" void kernel_launch(void* const* d_in, const int* in_sizes, int n_in,
                              void* d_out, int out_size)
{
    const float* H0in  = (const float*)d_in[0];
    const float* lin_w = (const float*)d_in[1];
    const float* lin_b = (const float*)d_in[2];
    const float* g0w   = (const float*)d_in[3];
    const float* g0b   = (const float*)d_in[4];
    const float* g1w   = (const float*)d_in[5];
    const float* g1b   = (const float*)d_in[6];

    cudaFuncSetAttribute(lattice_mma,
                         cudaFuncAttributeMaxDynamicSharedMemorySize, SMEM_TOTAL);

    convert_weights<<<96, 256>>>(lin_w, g0w, g1w);
    lattice_mma<<<NBLK, NTHR, SMEM_TOTAL>>>(H0in, lin_b, g0b, g1b, (float*)d_out);
}

// round 17
// speedup vs baseline: 2.2612x; 1.4546x over previous
#include <cuda_runtime.h>
#include <cuda_fp16.h>
#include <cstdint>

#define H_    512
#define B_    128
#define T_    512
#define L_    4
#define J_    2
#define NBLK  128
#define NTHR  512
#define BH    (B_ * H_)

// ---- stage-1 smem slot (3-slot ring): A 64x128k fp16, W 32x128k fp16 ----
#define S1_ROWB 272
#define S1_W_HI 17408
#define S1_SZ   26112
// ---- stage-2 smem slot (3-slot ring): A 32x(2x128k), W 32x(2x128k) ----
#define S2_ROWB 528
#define S2_W_HI 16896
#define S2_SZ   33792
#define P_OFF   78336                // 3*S1_SZ: stage-1 partial scratch (16KB)
#define SMEM_TOTAL (3 * S2_SZ)       // 101376

// ---- converted weights (fp16, transposed to [n][k]) ----
__device__ __half d_linw[8u * 2048u * 1024u];
__device__ __half d_gw[8u * 1024u * 1024u];    // n<512: g0w, n>=512: g1w

// ---- per-layer wavefront state (fp32 exact + single fp16 GEMM plane) ----
__device__ __align__(128) float d_zL[L_][B_ * 1024];
__device__ __align__(128) float d_h0mid[L_][BH], d_h1mid[L_][BH];
__device__ __align__(128) float d_h0out[2][L_][BH];
__device__ __align__(128) float d_H1[L_][BH];
__device__ __align__(128) __half d_h0midh[L_][BH], d_h1midh[L_][BH];
__device__ __align__(128) __half d_h0outh[2][L_][BH];
__device__ __align__(128) __half d_H1h[L_][BH];
__device__ __align__(128) __half d_x0h[2][BH];
__device__ __align__(128) __half d_arh[L_][BH], d_aqh[L_][BH];
__device__ unsigned int g_bar = 0;

// ================= helpers =================
__device__ __forceinline__ uint32_t smem_u32(const void* p) {
    uint32_t a;
    asm("{ .reg .u64 t; cvta.to.shared.u64 t, %1; cvt.u32.u64 %0, t; }"
        : "=r"(a) : "l"(p));
    return a;
}
__device__ __forceinline__ void cpa16(uint32_t d, const void* s) {
    asm volatile("cp.async.cg.shared.global [%0], [%1], 16;" :: "r"(d), "l"(s));
}
__device__ __forceinline__ void cp_commit() {
    asm volatile("cp.async.commit_group;" ::: "memory");
}
template <int N>
__device__ __forceinline__ void cp_wait() {
    asm volatile("cp.async.wait_group %0;" :: "n"(N) : "memory");
}
__device__ __forceinline__ void ldm_x4(uint32_t* r, uint32_t addr) {
    asm volatile("ldmatrix.sync.aligned.m8n8.x4.shared.b16 {%0,%1,%2,%3}, [%4];"
                 : "=r"(r[0]), "=r"(r[1]), "=r"(r[2]), "=r"(r[3]) : "r"(addr));
}
__device__ __forceinline__ void mma16816(float* c, const uint32_t* a, const uint32_t* b) {
    asm volatile(
        "mma.sync.aligned.m16n8k16.row.col.f32.f16.f16.f32 "
        "{%0,%1,%2,%3}, {%4,%5,%6,%7}, {%8,%9}, {%0,%1,%2,%3};"
        : "+f"(c[0]), "+f"(c[1]), "+f"(c[2]), "+f"(c[3])
        : "r"(a[0]), "r"(a[1]), "r"(a[2]), "r"(a[3]), "r"(b[0]), "r"(b[1]));
}
__device__ __forceinline__ uint32_t pack2(float x, float y) {
    __half2 h = __floats2half2_rn(x, y);
    return *reinterpret_cast<uint32_t*>(&h);
}
__device__ __forceinline__ float sigf(float v) { return 1.f / (1.f + __expf(-v)); }
__device__ __forceinline__ void grid_barrier() {
    __syncthreads();
    if (threadIdx.x == 0) {
        __threadfence();
        unsigned ticket = atomicAdd(&g_bar, 1u);
        unsigned target = (ticket & ~(unsigned)(NBLK - 1)) + NBLK;
        while ((int)(*(volatile unsigned*)&g_bar - target) < 0) { __nanosleep(20); }
        __threadfence();
    }
    __syncthreads();
}

// ============ weight pre-conversion: fp32 [k][n] -> fp16 [n][k] ============
__global__ void convert_weights(const float* __restrict__ lin_w,
                                const float* __restrict__ g0w,
                                const float* __restrict__ g1w) {
    int t = blockIdx.x * blockDim.x + threadIdx.x;
    const float* src;
    int stride;
    __half* dh;
    if (t < 8 * 2048) {
        int cell = t >> 11, n = t & 2047;
        src = lin_w + (size_t)cell * 1024 * 2048 + n;
        stride = 2048;
        dh = d_linw + (size_t)t * 1024;
    } else {
        int t2 = t - 8 * 2048;
        if (t2 >= 8 * 1024) return;
        int cell = t2 >> 10, n = t2 & 1023;
        src = (n < 512) ? (g0w + (size_t)cell * 1024 * 512 + n)
                        : (g1w + (size_t)cell * 1024 * 512 + (n - 512));
        stride = 512;
        dh = d_gw + (size_t)t2 * 1024;
    }
    for (int k0 = 0; k0 < 1024; k0 += 8) {
        unsigned short hb[8];
#pragma unroll
        for (int i = 0; i < 8; ++i) {
            __half v = __float2half(src[(size_t)(k0 + i) * stride]);
            hb[i] = *reinterpret_cast<unsigned short*>(&v);
        }
        *(uint4*)(dh + k0) = *(uint4*)hb;
    }
}

// ====== 4 k-steps of a resident chunk, 16x16 warp tile, single fp16 pass ======
__device__ __forceinline__ void compute4(
    uint32_t base, uint32_t aOff, uint32_t wOff, float* acc)
{
#pragma unroll
    for (int s = 0; s < 4; ++s) {
        uint32_t ah[4], bh[4];
        ldm_x4(ah, base + aOff + s * 32);
        ldm_x4(bh, base + wOff + s * 32);
        mma16816(acc,     ah, bh);
        mma16816(acc + 4, ah, bh + 2);
    }
}

// ====== stage-1 GEMM: C[64 x 32], warps 4m x 2n x 2k, warp tile 16x16 ======
__device__ __forceinline__ void gemm_s1(
    uint32_t smb, char* smraw, int mbase, int nbase,
    const __half* __restrict__ a0, const __half* __restrict__ a1,
    const __half* __restrict__ wh)
{
    const int tid = threadIdx.x, lane = tid & 31, wid = tid >> 5;
    const int wm = wid & 3, wn = (wid >> 2) & 1, wk = wid >> 3;
    const int g = lane >> 2, tg = lane & 3;
    float acc[8];
#pragma unroll
    for (int i = 0; i < 8; ++i) acc[i] = 0.f;

    const uint32_t aOff = (uint32_t)(wm * 16 + (lane & 15)) * S1_ROWB +
                          (lane >> 4) * 16 + wk * 128;
    const uint32_t wOff = S1_W_HI +
                          (uint32_t)(wn * 16 + (lane & 7) + ((lane >> 4) & 1) * 8) *
                              S1_ROWB + ((lane >> 3) & 1) * 16 + wk * 128;

    const int arow = tid >> 3, agr = (tid & 7) * 2;
    const int wrow = tid >> 4, wgr = tid & 15;

    auto issue = [&](int kc) {
        const uint32_t st = smb + (uint32_t)(kc % 3) * S1_SZ;
        const __half* ah = (kc < 4) ? a0 : a1;
        const int koff = (kc & 3) * 128;
        const __half* srh = ah + (size_t)(mbase + arow) * 512 + koff + agr * 8;
        const uint32_t dA = st + (uint32_t)arow * S1_ROWB + agr * 16;
        cpa16(dA, srh);  cpa16(dA + 16, srh + 8);
        cpa16(st + S1_W_HI + (uint32_t)wrow * S1_ROWB + wgr * 16,
              wh + (size_t)(nbase + wrow) * 1024 + kc * 128 + wgr * 8);
        cp_commit();
    };

    issue(0); issue(1);
    for (int kc = 0; kc < 8; ++kc) {
        if (kc < 7) cp_wait<1>(); else cp_wait<0>();
        __syncthreads();
        if (kc + 2 < 8) issue(kc + 2);
        compute4(smb + (uint32_t)(kc % 3) * S1_SZ, aOff, wOff, acc);
    }
    // publish partials: P[wk(2)][m(64)][n(32)]
    float* P = (float*)(smraw + P_OFF);
#pragma unroll
    for (int nt = 0; nt < 2; ++nt)
#pragma unroll
        for (int rr = 0; rr < 2; ++rr) {
            const int m = wm * 16 + rr * 8 + g;
            const int n = wn * 16 + nt * 8 + tg * 2;
            *(float2*)&P[(wk << 11) + m * 32 + n] =
                make_float2(acc[nt * 4 + rr * 2], acc[nt * 4 + rr * 2 + 1]);
        }
    __syncthreads();
}

// ====== stage-2 GEMM: C[32 x 32], warps 2m x 2n x 4k, warp tile 16x16 ======
__device__ __forceinline__ void gemm_s2(
    uint32_t smb, char* smraw, int mbase, int nbase,
    const __half* __restrict__ s0, const __half* __restrict__ s1,
    const __half* __restrict__ wh)
{
    const int tid = threadIdx.x, lane = tid & 31, wid = tid >> 5;
    const int wm = wid & 1, wn = (wid >> 1) & 1, wk = wid >> 2;
    const int g = lane >> 2, tg = lane & 3;
    float acc[8];
#pragma unroll
    for (int i = 0; i < 8; ++i) acc[i] = 0.f;

    const uint32_t aOff = (uint32_t)(wm * 16 + (lane & 15)) * S2_ROWB +
                          (lane >> 4) * 16 + wk * 128;
    const uint32_t wOff = S2_W_HI +
                          (uint32_t)(wn * 16 + (lane & 7) + ((lane >> 4) & 1) * 8) *
                              S2_ROWB + ((lane >> 3) & 1) * 16 + wk * 128;

    const int arow = tid >> 4, agr = (tid & 15) * 2;
    const int wwrow = tid >> 4, wgb = (tid & 15) * 2;

    auto issue = [&](int kc) {
        const uint32_t st = smb + (uint32_t)(kc % 3) * S2_SZ;
#pragma unroll
        for (int i = 0; i < 2; ++i) {
            int gidx = agr + i;
            const __half* ph = (gidx < 16) ? s0 : s1;
            int kk = kc * 128 + (gidx & 15) * 8;
            cpa16(st + (uint32_t)arow * S2_ROWB + gidx * 16,
                  ph + (size_t)(mbase + arow) * 512 + kk);
        }
        const uint32_t wdst = st + S2_W_HI + (uint32_t)wwrow * S2_ROWB;
#pragma unroll
        for (int i = 0; i < 2; ++i) {
            int gidx = wgb + i;
            int kk = (gidx < 16) ? (kc * 128 + gidx * 8)
                                 : (512 + kc * 128 + (gidx - 16) * 8);
            cpa16(wdst + gidx * 16, wh + (size_t)(nbase + wwrow) * 1024 + kk);
        }
        cp_commit();
    };

    issue(0); issue(1);
    for (int kc = 0; kc < 4; ++kc) {
        if (kc < 3) cp_wait<1>(); else cp_wait<0>();
        __syncthreads();
        if (kc + 2 < 4) issue(kc + 2);
        compute4(smb + (uint32_t)(kc % 3) * S2_SZ, aOff, wOff, acc);
    }
    // publish partials: P2[wk(4)][m(32)][n(32)] (slot-1 region, dead by now)
    float* P2 = (float*)(smraw + S2_SZ);
#pragma unroll
    for (int nt = 0; nt < 2; ++nt)
#pragma unroll
        for (int rr = 0; rr < 2; ++rr) {
            const int m = wm * 16 + rr * 8 + g;
            const int n = wn * 16 + nt * 8 + tg * 2;
            *(float2*)&P2[((wk << 5) + m) * 32 + n] =
                make_float2(acc[nt * 4 + rr * 2], acc[nt * 4 + rr * 2 + 1]);
        }
    __syncthreads();
}

// =================== main persistent kernel ===================
__global__ void __launch_bounds__(NTHR, 1) lattice_mma(
    const float* __restrict__ H0in,
    const float* __restrict__ lin_b,
    const float* __restrict__ g0b, const float* __restrict__ g1b,
    float* __restrict__ out)
{
    extern __shared__ __align__(16) char smraw[];
    const uint32_t smb = smem_u32(smraw);

    const int tid = threadIdx.x;
    const int blk = blockIdx.x;

    for (int i = tid + blk * NTHR; i < L_ * BH; i += NBLK * NTHR) {
        d_H1[0][i] = 0.f;
        d_H1h[0][i] = __float2half(0.f);
    }
    for (int e = tid + blk * NTHR; e < BH; e += NBLK * NTHR) {
        int b = e >> 9, h = e & (H_ - 1);
        d_x0h[0][e] = __float2half(__ldg(&H0in[(size_t)b * T_ * H_ + h]));
    }
    grid_barrier();

    float* out_h1 = out + (size_t)B_ * T_ * H_;

    const int m1base = (blk & 1) * 64, n1base = (blk >> 1) * 32;
    const int m2base = (blk & 3) * 32, n2base = (blk >> 2) * 32;
    const bool g0side = (n2base < 512);
    const int region = n1base >> 9;            // 0,1: z   2: r   3: q

    const int e1m = tid >> 3, e1n = (tid & 7) * 4;
    const int e2m = tid >> 4, e2n = (tid & 15) * 2;

    for (int s = 0; s < T_ + L_ - 1; ++s) {
        const int par = s & 1;
        for (int jj = 0; jj < J_; ++jj) {
            // =============== stage 1: all active layers ===============
            for (int l = 0; l < L_; ++l) {
                const int t = s - l;
                if (t < 0 || t >= T_) continue;
                const int cell = l * J_ + jj;

                const float* h0src;
                int lda0;
                const __half *h0sh, *h1sh;
                const float* h1src;
                if (jj == 0) {
                    h1src = d_H1[l];
                    h1sh = d_H1h[l];
                    if (l == 0) {
                        h0src = H0in + (size_t)t * H_;  lda0 = T_ * H_;
                        h0sh = d_x0h[par];
                    } else {
                        h0src = d_h0out[par ^ 1][l - 1];  lda0 = H_;
                        h0sh = d_h0outh[par ^ 1][l - 1];
                    }
                } else {
                    h0src = d_h0mid[l];  lda0 = H_;
                    h0sh = d_h0midh[l];
                    h1src = d_h1mid[l];
                    h1sh = d_h1midh[l];
                }

                gemm_s1(smb, smraw, m1base, n1base,
                        h0sh, h1sh, d_linw + (size_t)cell * 2048 * 1024);

                const float* P = (const float*)(smraw + P_OFF);
                float4 p0 = *(const float4*)&P[e1m * 32 + e1n];
                float4 p1 = *(const float4*)&P[2048 + e1m * 32 + e1n];
                const int   mrow = m1base + e1m;
                const int   col  = n1base + e1n;
                const float* bp  = lin_b + (size_t)cell * 2048 + col;
                const float s0 = sigf(p0.x + p1.x + bp[0]);
                const float s1 = sigf(p0.y + p1.y + bp[1]);
                const float s2 = sigf(p0.z + p1.z + bp[2]);
                const float s3 = sigf(p0.w + p1.w + bp[3]);
                if (region < 2) {
                    *(float4*)&d_zL[l][mrow * 1024 + col] =
                        make_float4(s0, s1, s2, s3);
                } else if (region == 2) {
                    const int cc = col - 1024;
                    float4 h = __ldcg((const float4*)&h1src[mrow * H_ + cc]);
                    *(uint2*)&d_arh[l][mrow * H_ + cc] =
                        make_uint2(pack2(s0 * h.x, s1 * h.y),
                                   pack2(s2 * h.z, s3 * h.w));
                } else {
                    const int cc = col - 1536;
                    float4 h = __ldcg((const float4*)&h0src[(size_t)mrow * lda0 + cc]);
                    *(uint2*)&d_aqh[l][mrow * H_ + cc] =
                        make_uint2(pack2(s0 * h.x, s1 * h.y),
                                   pack2(s2 * h.z, s3 * h.w));
                }
                __syncthreads();
            }
            grid_barrier();

            // =============== stage 2: all active layers ===============
            for (int l = 0; l < L_; ++l) {
                const int t = s - l;
                if (t < 0 || t >= T_) continue;
                const int  cell = l * J_ + jj;
                const bool last = (jj == 1) && (l == L_ - 1);

                const float* h0src;
                int lda0;
                const __half *h0sh, *h1sh;
                const float* h1src;
                if (jj == 0) {
                    h1src = d_H1[l];
                    h1sh = d_H1h[l];
                    if (l == 0) {
                        h0src = H0in + (size_t)t * H_;  lda0 = T_ * H_;
                        h0sh = d_x0h[par];
                    } else {
                        h0src = d_h0out[par ^ 1][l - 1];  lda0 = H_;
                        h0sh = d_h0outh[par ^ 1][l - 1];
                    }
                } else {
                    h0src = d_h0mid[l];  lda0 = H_;
                    h0sh = d_h0midh[l];
                    h1src = d_h1mid[l];
                    h1sh = d_h1midh[l];
                }

                const __half* a0 = g0side ? h0sh : h1sh;
                const __half* a1 = g0side ? d_arh[l] : d_aqh[l];
                gemm_s2(smb, smraw, m2base, n2base,
                        a0, a1, d_gw + (size_t)cell * 1024 * 1024);

                const float* P2 = (const float*)(smraw + S2_SZ);
                float2 q0 = *(const float2*)&P2[e2m * 32 + e2n];
                float2 q1 = *(const float2*)&P2[1024 + e2m * 32 + e2n];
                float2 q2 = *(const float2*)&P2[2048 + e2m * 32 + e2n];
                float2 q3 = *(const float2*)&P2[3072 + e2m * 32 + e2n];
                const float v0 = q0.x + q1.x + q2.x + q3.x;
                const float v1 = q0.y + q1.y + q2.y + q3.y;
                const int mrow = m2base + e2m;
                const int col  = n2base + e2n;
                if (g0side) {
                    float* h1dst = (jj == 1) ? d_H1[l] : d_h1mid[l];
                    __half* h1dh = (jj == 1) ? d_H1h[l] : d_h1midh[l];
                    const float* bp = g0b + (size_t)cell * H_ + col;
                    const float c0 = tanhf(v0 + bp[0]);
                    const float c1 = tanhf(v1 + bp[1]);
                    float2 z = __ldcg((const float2*)&d_zL[l][mrow * 1024 + H_ + col]);
                    float2 o = __ldcg((const float2*)&h1src[mrow * H_ + col]);
                    const float n0v = z.x * c0 + (1.f - z.x) * o.x;
                    const float n1v = z.y * c1 + (1.f - z.y) * o.y;
                    *(float2*)&h1dst[mrow * H_ + col] = make_float2(n0v, n1v);
                    *(uint32_t*)&h1dh[mrow * H_ + col] = pack2(n0v, n1v);
                } else {
                    const int n2 = col - 512;
                    float* h0dst = last ? (out + (size_t)t * H_)
                                        : ((jj == 1) ? d_h0out[par][l] : d_h0mid[l]);
                    const int ldh0d = last ? (T_ * H_) : H_;
                    const float* bp = g1b + (size_t)cell * H_ + n2;
                    const float c0 = tanhf(v0 + bp[0]);
                    const float c1 = tanhf(v1 + bp[1]);
                    float2 z = __ldcg((const float2*)&d_zL[l][mrow * 1024 + n2]);
                    float2 o = __ldcg((const float2*)&h0src[(size_t)mrow * lda0 + n2]);
                    const float n0v = z.x * c0 + (1.f - z.x) * o.x;
                    const float n1v = z.y * c1 + (1.f - z.y) * o.y;
                    *(float2*)&h0dst[(size_t)mrow * ldh0d + n2] = make_float2(n0v, n1v);
                    if (!last) {
                        __half* h0dh = (jj == 1) ? d_h0outh[par][l] : d_h0midh[l];
                        *(uint32_t*)&h0dh[mrow * H_ + n2] = pack2(n0v, n1v);
                    }
                }
                __syncthreads();
            }

            // prepare next step's input fp16 plane
            if (jj == 1 && s + 1 < T_) {
                const int np = (s + 1) & 1;
                for (int e = tid + blk * NTHR; e < BH; e += NBLK * NTHR) {
                    int b = e >> 9, h = e & (H_ - 1);
                    d_x0h[np][e] =
                        __float2half(__ldg(&H0in[((size_t)b * T_ + (s + 1)) * H_ + h]));
                }
            }
            grid_barrier();
        }
    }

    // H1_final: out2[b, l, h] = d_H1[l][b*H + h]
    for (int i = tid + blk * NTHR; i < L_ * BH; i += NBLK * NTHR) {
        int h    = i & (H_ - 1);
        int rest = i >> 9;
        int b    = rest & (B_ - 1);
        int l    = rest >> 7;
        out_h1[((size_t)b * L_ + l) * H_ + h] = __ldcg(&d_H1[0][i]);
    }
}

extern "C" void kernel_launch(void* const* d_in, const int* in_sizes, int n_in,
                              void* d_out, int out_size)
{
    const float* H0in  = (const float*)d_in[0];
    const float* lin_w = (const float*)d_in[1];
    const float* lin_b = (const float*)d_in[2];
    const float* g0w   = (const float*)d_in[3];
    const float* g0b   = (const float*)d_in[4];
    const float* g1w   = (const float*)d_in[5];
    const float* g1b   = (const float*)d_in[6];

    cudaFuncSetAttribute(lattice_mma,
                         cudaFuncAttributeMaxDynamicSharedMemorySize, SMEM_TOTAL);

    convert_weights<<<96, 256>>>(lin_w, g0w, g1w);
    lattice_mma<<<NBLK, NTHR, SMEM_TOTAL>>>(H0in, lin_b, g0b, g1b, (float*)d_out);
}